// round 1
// baseline (speedup 1.0000x reference)
#include <cuda_runtime.h>
#include <math.h>

#define BB 2
#define HH 16
#define DD 64
#define CC 1024
#define TEXT_N 226
#define NTOK_N 1024
#define TOK_N 4096
#define SQ (TEXT_N + NTOK_N)   /* 1250 */
#define SKV (TEXT_N + TOK_N)   /* 4322 */
#define N3C (3*CC)             /* 3072 */

// ---------------- scratch (module-load allocated, allowed) ----------------
__device__ float g_wqkv [CC * N3C];            // packed [K=1024][N=3072]
__device__ float g_qkv  [BB * SQ * N3C];       // [2500, 3072] q|k|v
__device__ float g_kraw [BB * SKV * CC];       // scattered key cache
__device__ float g_vraw [BB * SKV * CC];       // scattered value cache
__device__ float g_khead[BB * HH * SKV * DD];  // LN+rope, [B,H,Skv,D]
__device__ float g_vhead[BB * HH * SKV * DD];  // [B,H,Skv,D]
__device__ float g_qhead[BB * HH * SQ * DD];   // LN+rope, [B,H,Sq,D]
__device__ float g_attn [BB * SQ * CC];        // attention out [B,Sq,C]

// ---------------- pack Wq|Wk|Wv -> [K, 3C] ----------------
__global__ void pack_w_kernel(const float* __restrict__ Wq,
                              const float* __restrict__ Wk,
                              const float* __restrict__ Wv) {
    int i = blockIdx.x * blockDim.x + threadIdx.x;
    const int tot4 = CC * N3C / 4;
    if (i >= tot4) return;
    int k = i / (N3C / 4);
    int n = (i % (N3C / 4)) * 4;
    const float* src = (n < CC)   ? (Wq + (size_t)k * CC + n)
                     : (n < 2*CC) ? (Wk + (size_t)k * CC + (n - CC))
                                  : (Wv + (size_t)k * CC + (n - 2*CC));
    ((float4*)g_wqkv)[i] = *(const float4*)src;
}

// ---------------- QKV GEMM: [2500,1024] @ [1024,3072] ----------------
__global__ __launch_bounds__(256) void gemm_qkv_kernel(const float* __restrict__ hid,
                                                       const float* __restrict__ enc) {
    const int M = BB * SQ;  // 2500
    __shared__ float As[16][64];
    __shared__ float Bs[16][64];
    const int tid = threadIdx.x;
    const int m0 = blockIdx.y * 64;
    const int n0 = blockIdx.x * 64;
    const int arow  = tid >> 2;
    const int acol4 = (tid & 3) * 4;
    const int brow  = tid >> 4;
    const int bcol  = (tid & 15) * 4;
    const int ty = tid >> 4, tx = tid & 15;

    const float* asrc = nullptr;
    {
        int grow = m0 + arow;
        if (grow < M) {
            int b = grow / SQ, s = grow % SQ;
            asrc = (s < TEXT_N) ? (enc + ((size_t)b * TEXT_N + s) * CC)
                                : (hid + ((size_t)b * NTOK_N + (s - TEXT_N)) * CC);
        }
    }
    float cacc[4][4];
#pragma unroll
    for (int i = 0; i < 4; i++)
#pragma unroll
        for (int j = 0; j < 4; j++) cacc[i][j] = 0.f;

    for (int kk = 0; kk < CC; kk += 16) {
        float4 av = asrc ? *(const float4*)(asrc + kk + acol4) : make_float4(0,0,0,0);
        As[acol4+0][arow] = av.x; As[acol4+1][arow] = av.y;
        As[acol4+2][arow] = av.z; As[acol4+3][arow] = av.w;
        *(float4*)&Bs[brow][bcol] =
            *(const float4*)(g_wqkv + (size_t)(kk + brow) * N3C + n0 + bcol);
        __syncthreads();
#pragma unroll
        for (int k = 0; k < 16; k++) {
            float a[4], bv[4];
#pragma unroll
            for (int i = 0; i < 4; i++) a[i] = As[k][ty*4+i];
#pragma unroll
            for (int j = 0; j < 4; j++) bv[j] = Bs[k][tx*4+j];
#pragma unroll
            for (int i = 0; i < 4; i++)
#pragma unroll
                for (int j = 0; j < 4; j++) cacc[i][j] += a[i] * bv[j];
        }
        __syncthreads();
    }
#pragma unroll
    for (int i = 0; i < 4; i++) {
        int row = m0 + ty*4 + i;
        if (row < M) {
            float4 t;
            t.x = cacc[i][0]; t.y = cacc[i][1]; t.z = cacc[i][2]; t.w = cacc[i][3];
            *(float4*)(g_qkv + (size_t)row * N3C + n0 + tx*4) = t;
        }
    }
}

// ---------------- cache copy + scatter of new K/V ----------------
__global__ void copy_cache_kernel(const float* __restrict__ kc,
                                  const float* __restrict__ vc) {
    int i = blockIdx.x * blockDim.x + threadIdx.x;
    const int tot4 = BB * SKV * CC / 4;
    if (i < tot4) {
        ((float4*)g_kraw)[i] = ((const float4*)kc)[i];
        ((float4*)g_vraw)[i] = ((const float4*)vc)[i];
    }
}

__global__ void scatter_kernel(const int* __restrict__ tok) {
    int i = blockIdx.x * blockDim.x + threadIdx.x;
    const int tot4 = BB * SQ * (CC / 4);
    if (i >= tot4) return;
    int r  = i / (CC / 4);
    int c4 = (i % (CC / 4)) * 4;
    int b = r / SQ, s = r % SQ;
    int p = (s < TEXT_N) ? s : (TEXT_N + tok[s - TEXT_N]);
    size_t src = (size_t)r * N3C + CC + c4;
    size_t dst = ((size_t)b * SKV + p) * CC + c4;
    *(float4*)(g_kraw + dst) = *(const float4*)(g_qkv + src);
    *(float4*)(g_vraw + dst) = *(const float4*)(g_qkv + src + CC);
}

// ---------------- K: per-head LN + rope + transpose; V: transpose ----------------
__global__ __launch_bounds__(512) void kv_norm_kernel(const float* __restrict__ gk,
                                                      const float* __restrict__ bk,
                                                      const float* __restrict__ rc,
                                                      const float* __restrict__ rs) {
    const int bp = blockIdx.x;            // b * SKV + p
    const int b = bp / SKV, p = bp % SKV;
    const int w = threadIdx.x >> 5;       // head 0..15
    const int lid = threadIdx.x & 31;     // dims {2*lid, 2*lid+1}
    size_t base = (size_t)bp * CC + w * DD + 2 * lid;
    float2 x = *(const float2*)(g_kraw + base);
    float sum = x.x + x.y;
    float sq  = x.x * x.x + x.y * x.y;
#pragma unroll
    for (int off = 16; off; off >>= 1) {
        sum += __shfl_xor_sync(0xffffffffu, sum, off);
        sq  += __shfl_xor_sync(0xffffffffu, sq,  off);
    }
    float mean = sum * (1.0f / 64.0f);
    float var  = sq * (1.0f / 64.0f) - mean * mean;
    float rsig = rsqrtf(var + 1e-6f);
    float y0 = (x.x - mean) * rsig * gk[2*lid]   + bk[2*lid];
    float y1 = (x.y - mean) * rsig * gk[2*lid+1] + bk[2*lid+1];
    float o0 = y0, o1 = y1;
    if (p >= TEXT_N) {
        int rp = p - TEXT_N;
        float2 c  = *(const float2*)(rc + (size_t)rp * DD + 2 * lid);
        float2 sn = *(const float2*)(rs + (size_t)rp * DD + 2 * lid);
        o0 = y0 * c.x - y1 * sn.x;
        o1 = y1 * c.y + y0 * sn.y;
    }
    size_t ob = (((size_t)(b * HH + w)) * SKV + p) * DD + 2 * lid;
    *(float2*)(g_khead + ob) = make_float2(o0, o1);
    float2 v = *(const float2*)(g_vraw + base);
    *(float2*)(g_vhead + ob) = v;
}

// ---------------- Q: per-head LN + rope + transpose ----------------
__global__ __launch_bounds__(512) void q_norm_kernel(const float* __restrict__ gq,
                                                     const float* __restrict__ bq,
                                                     const float* __restrict__ rc,
                                                     const float* __restrict__ rs,
                                                     const int* __restrict__ tok) {
    const int bs = blockIdx.x;            // b * SQ + s
    const int b = bs / SQ, s = bs % SQ;
    const int w = threadIdx.x >> 5;
    const int lid = threadIdx.x & 31;
    size_t base = (size_t)bs * N3C + w * DD + 2 * lid;
    float2 x = *(const float2*)(g_qkv + base);
    float sum = x.x + x.y;
    float sq  = x.x * x.x + x.y * x.y;
#pragma unroll
    for (int off = 16; off; off >>= 1) {
        sum += __shfl_xor_sync(0xffffffffu, sum, off);
        sq  += __shfl_xor_sync(0xffffffffu, sq,  off);
    }
    float mean = sum * (1.0f / 64.0f);
    float var  = sq * (1.0f / 64.0f) - mean * mean;
    float rsig = rsqrtf(var + 1e-6f);
    float y0 = (x.x - mean) * rsig * gq[2*lid]   + bq[2*lid];
    float y1 = (x.y - mean) * rsig * gq[2*lid+1] + bq[2*lid+1];
    float o0 = y0, o1 = y1;
    if (s >= TEXT_N) {
        int rp = tok[s - TEXT_N];
        float2 c  = *(const float2*)(rc + (size_t)rp * DD + 2 * lid);
        float2 sn = *(const float2*)(rs + (size_t)rp * DD + 2 * lid);
        o0 = y0 * c.x - y1 * sn.x;
        o1 = y1 * c.y + y0 * sn.y;
    }
    size_t ob = (((size_t)(b * HH + w)) * SQ + s) * DD + 2 * lid;
    *(float2*)(g_qhead + ob) = make_float2(o0, o1);
}

// ---------------- flash attention: 1 q-row per thread ----------------
__global__ __launch_bounds__(128) void attn_kernel() {
    const int bh = blockIdx.x;            // b*H + h
    const int b = bh >> 4;
    const int h = bh & 15;
    const int qrow = blockIdx.y * 128 + threadIdx.x;
    const bool valid = qrow < SQ;
    __shared__ float Ks[64 * 64];
    __shared__ float Vs[64 * 64];
    float q[64], acc[64];
    float mval = -1e30f, lval = 0.f;
    {
        int qr = valid ? qrow : (SQ - 1);
        const float4* qp = (const float4*)(g_qhead + (((size_t)bh) * SQ + qr) * DD);
#pragma unroll
        for (int d4 = 0; d4 < 16; d4++) {
            float4 t = qp[d4];
            q[d4*4+0] = t.x * 0.125f; q[d4*4+1] = t.y * 0.125f;
            q[d4*4+2] = t.z * 0.125f; q[d4*4+3] = t.w * 0.125f;
        }
    }
#pragma unroll
    for (int d = 0; d < 64; d++) acc[d] = 0.f;

    const float4* kbase = (const float4*)(g_khead + (size_t)bh * SKV * DD);
    const float4* vbase = (const float4*)(g_vhead + (size_t)bh * SKV * DD);

    for (int kt = 0; kt < SKV; kt += 64) {
        int rows = min(64, SKV - kt);
        int n4 = rows * 16;
        float4* K4 = (float4*)Ks;
        float4* V4 = (float4*)Vs;
        for (int i = threadIdx.x; i < n4; i += 128) {
            K4[i] = kbase[kt * 16 + i];
            V4[i] = vbase[kt * 16 + i];
        }
        __syncthreads();
        if (valid) {
            for (int j = 0; j < rows; j++) {
                const float4* kr = (const float4*)(Ks + j * 64);
                float sp[4] = {0.f, 0.f, 0.f, 0.f};
#pragma unroll
                for (int d4 = 0; d4 < 16; d4++) {
                    float4 kv = kr[d4];
                    sp[d4 & 3] += q[d4*4+0]*kv.x + q[d4*4+1]*kv.y
                                + q[d4*4+2]*kv.z + q[d4*4+3]*kv.w;
                }
                float s = (sp[0] + sp[1]) + (sp[2] + sp[3]);
                if (s > mval) {
                    float corr = __expf(mval - s);
                    lval *= corr;
#pragma unroll
                    for (int d = 0; d < 64; d++) acc[d] *= corr;
                    mval = s;
                }
                float p = __expf(s - mval);
                lval += p;
                const float4* vr = (const float4*)(Vs + j * 64);
#pragma unroll
                for (int d4 = 0; d4 < 16; d4++) {
                    float4 vv = vr[d4];
                    acc[d4*4+0] += p * vv.x; acc[d4*4+1] += p * vv.y;
                    acc[d4*4+2] += p * vv.z; acc[d4*4+3] += p * vv.w;
                }
            }
        }
        __syncthreads();
    }

    if (valid) {
        float inv = 1.0f / lval;
        float4* op = (float4*)(g_attn + ((size_t)(b * SQ + qrow)) * CC + h * DD);
#pragma unroll
        for (int d4 = 0; d4 < 16; d4++) {
            float4 t;
            t.x = acc[d4*4+0] * inv; t.y = acc[d4*4+1] * inv;
            t.z = acc[d4*4+2] * inv; t.w = acc[d4*4+3] * inv;
            op[d4] = t;
        }
    }
}

// ---------------- out GEMM: attn @ Wo + bo, fused output reorder ----------------
__global__ __launch_bounds__(256) void gemm_out_kernel(const float* __restrict__ Wo,
                                                       const float* __restrict__ bo,
                                                       float* __restrict__ out) {
    const int M = BB * SQ;
    __shared__ float As[16][64];
    __shared__ float Bs[16][64];
    const int tid = threadIdx.x;
    const int m0 = blockIdx.y * 64;
    const int n0 = blockIdx.x * 64;
    const int arow  = tid >> 2;
    const int acol4 = (tid & 3) * 4;
    const int brow  = tid >> 4;
    const int bcol  = (tid & 15) * 4;
    const int ty = tid >> 4, tx = tid & 15;

    const float* asrc = (m0 + arow < M) ? (g_attn + (size_t)(m0 + arow) * CC) : nullptr;

    float cacc[4][4];
#pragma unroll
    for (int i = 0; i < 4; i++)
#pragma unroll
        for (int j = 0; j < 4; j++) cacc[i][j] = 0.f;

    for (int kk = 0; kk < CC; kk += 16) {
        float4 av = asrc ? *(const float4*)(asrc + kk + acol4) : make_float4(0,0,0,0);
        As[acol4+0][arow] = av.x; As[acol4+1][arow] = av.y;
        As[acol4+2][arow] = av.z; As[acol4+3][arow] = av.w;
        *(float4*)&Bs[brow][bcol] =
            *(const float4*)(Wo + (size_t)(kk + brow) * CC + n0 + bcol);
        __syncthreads();
#pragma unroll
        for (int k = 0; k < 16; k++) {
            float a[4], bv[4];
#pragma unroll
            for (int i = 0; i < 4; i++) a[i] = As[k][ty*4+i];
#pragma unroll
            for (int j = 0; j < 4; j++) bv[j] = Bs[k][tx*4+j];
#pragma unroll
            for (int i = 0; i < 4; i++)
#pragma unroll
                for (int j = 0; j < 4; j++) cacc[i][j] += a[i] * bv[j];
        }
        __syncthreads();
    }
    float4 bias = *(const float4*)(bo + n0 + tx*4);
#pragma unroll
    for (int i = 0; i < 4; i++) {
        int row = m0 + ty*4 + i;
        if (row < M) {
            int b = row / SQ, s = row % SQ;
            size_t off = (s >= TEXT_N)
                ? ((size_t)(b * NTOK_N + (s - TEXT_N))) * CC
                : (size_t)BB * NTOK_N * CC + ((size_t)(b * TEXT_N + s)) * CC;
            float4 t;
            t.x = cacc[i][0] + bias.x; t.y = cacc[i][1] + bias.y;
            t.z = cacc[i][2] + bias.z; t.w = cacc[i][3] + bias.w;
            *(float4*)(out + off + n0 + tx*4) = t;
        }
    }
}

// ---------------- launch ----------------
extern "C" void kernel_launch(void* const* d_in, const int* in_sizes, int n_in,
                              void* d_out, int out_size) {
    const float* hid = (const float*)d_in[0];
    const float* enc = (const float*)d_in[1];
    const float* Wq  = (const float*)d_in[2];
    const float* Wk  = (const float*)d_in[3];
    const float* Wv  = (const float*)d_in[4];
    const float* Wo  = (const float*)d_in[5];
    const float* bo  = (const float*)d_in[6];
    const float* gq  = (const float*)d_in[7];
    const float* bq  = (const float*)d_in[8];
    const float* gk  = (const float*)d_in[9];
    const float* bk  = (const float*)d_in[10];
    const float* rc  = (const float*)d_in[11];
    const float* rs  = (const float*)d_in[12];
    const float* kc  = (const float*)d_in[13];
    const float* vc  = (const float*)d_in[14];
    const int*   tok = (const int*)d_in[15];
    float* out = (float*)d_out;

    pack_w_kernel<<<(CC * N3C / 4 + 255) / 256, 256>>>(Wq, Wk, Wv);
    gemm_qkv_kernel<<<dim3(N3C / 64, (BB * SQ + 63) / 64), 256>>>(hid, enc);
    copy_cache_kernel<<<(BB * SKV * CC / 4 + 255) / 256, 256>>>(kc, vc);
    scatter_kernel<<<(BB * SQ * (CC / 4) + 255) / 256, 256>>>(tok);
    kv_norm_kernel<<<BB * SKV, 512>>>(gk, bk, rc, rs);
    q_norm_kernel<<<BB * SQ, 512>>>(gq, bq, rc, rs, tok);
    attn_kernel<<<dim3(BB * HH, (SQ + 127) / 128), 128>>>();
    gemm_out_kernel<<<dim3(CC / 64, (BB * SQ + 63) / 64), 256>>>(Wo, bo, out);
}

// round 2
// speedup vs baseline: 1.0014x; 1.0014x over previous
#include <cuda_runtime.h>
#include <math.h>

#define BB 2
#define HH 16
#define DD 64
#define CC 1024
#define TEXT_N 226
#define NTOK_N 1024
#define TOK_N 4096
#define SQ (TEXT_N + NTOK_N)   /* 1250 */
#define SKV (TEXT_N + TOK_N)   /* 4322 */
#define N3C (3*CC)             /* 3072 */

// ---------------- scratch (module-load allocated, allowed) ----------------
__device__ float g_wqkv [CC * N3C];            // packed [K=1024][N=3072]
__device__ float g_qkv  [BB * SQ * N3C];       // [2500, 3072] q|k|v
__device__ float g_kraw [BB * SKV * CC];       // scattered key cache
__device__ float g_vraw [BB * SKV * CC];       // scattered value cache
__device__ float g_khead[BB * HH * SKV * DD];  // LN+rope, [B,H,Skv,D]
__device__ float g_vhead[BB * HH * SKV * DD];  // [B,H,Skv,D]
__device__ float g_qhead[BB * HH * SQ * DD];   // LN+rope, [B,H,Sq,D]
__device__ float g_attn [BB * SQ * CC];        // attention out [B,Sq,C]

// ---------------- pack Wq|Wk|Wv -> [K, 3C] ----------------
__global__ void pack_w_kernel(const float* __restrict__ Wq,
                              const float* __restrict__ Wk,
                              const float* __restrict__ Wv) {
    int i = blockIdx.x * blockDim.x + threadIdx.x;
    const int tot4 = CC * N3C / 4;
    if (i >= tot4) return;
    int k = i / (N3C / 4);
    int n = (i % (N3C / 4)) * 4;
    const float* src = (n < CC)   ? (Wq + (size_t)k * CC + n)
                     : (n < 2*CC) ? (Wk + (size_t)k * CC + (n - CC))
                                  : (Wv + (size_t)k * CC + (n - 2*CC));
    ((float4*)g_wqkv)[i] = *(const float4*)src;
}

// ---------------- QKV GEMM: [2500,1024] @ [1024,3072] ----------------
__global__ __launch_bounds__(256) void gemm_qkv_kernel(const float* __restrict__ hid,
                                                       const float* __restrict__ enc) {
    const int M = BB * SQ;  // 2500
    __shared__ float As[16][64];
    __shared__ float Bs[16][64];
    const int tid = threadIdx.x;
    const int m0 = blockIdx.y * 64;
    const int n0 = blockIdx.x * 64;
    const int arow  = tid >> 2;
    const int acol4 = (tid & 3) * 4;
    const int brow  = tid >> 4;
    const int bcol  = (tid & 15) * 4;
    const int ty = tid >> 4, tx = tid & 15;

    const float* asrc = nullptr;
    {
        int grow = m0 + arow;
        if (grow < M) {
            int b = grow / SQ, s = grow % SQ;
            asrc = (s < TEXT_N) ? (enc + ((size_t)b * TEXT_N + s) * CC)
                                : (hid + ((size_t)b * NTOK_N + (s - TEXT_N)) * CC);
        }
    }
    float cacc[4][4];
#pragma unroll
    for (int i = 0; i < 4; i++)
#pragma unroll
        for (int j = 0; j < 4; j++) cacc[i][j] = 0.f;

    for (int kk = 0; kk < CC; kk += 16) {
        float4 av = asrc ? *(const float4*)(asrc + kk + acol4) : make_float4(0,0,0,0);
        As[acol4+0][arow] = av.x; As[acol4+1][arow] = av.y;
        As[acol4+2][arow] = av.z; As[acol4+3][arow] = av.w;
        *(float4*)&Bs[brow][bcol] =
            *(const float4*)(g_wqkv + (size_t)(kk + brow) * N3C + n0 + bcol);
        __syncthreads();
#pragma unroll
        for (int k = 0; k < 16; k++) {
            float a[4], bv[4];
#pragma unroll
            for (int i = 0; i < 4; i++) a[i] = As[k][ty*4+i];
#pragma unroll
            for (int j = 0; j < 4; j++) bv[j] = Bs[k][tx*4+j];
#pragma unroll
            for (int i = 0; i < 4; i++)
#pragma unroll
                for (int j = 0; j < 4; j++) cacc[i][j] += a[i] * bv[j];
        }
        __syncthreads();
    }
#pragma unroll
    for (int i = 0; i < 4; i++) {
        int row = m0 + ty*4 + i;
        if (row < M) {
            float4 t;
            t.x = cacc[i][0]; t.y = cacc[i][1]; t.z = cacc[i][2]; t.w = cacc[i][3];
            *(float4*)(g_qkv + (size_t)row * N3C + n0 + tx*4) = t;
        }
    }
}

// ---------------- cache copy + scatter of new K/V ----------------
__global__ void copy_cache_kernel(const float* __restrict__ kc,
                                  const float* __restrict__ vc) {
    int i = blockIdx.x * blockDim.x + threadIdx.x;
    const int tot4 = BB * SKV * CC / 4;
    if (i < tot4) {
        ((float4*)g_kraw)[i] = ((const float4*)kc)[i];
        ((float4*)g_vraw)[i] = ((const float4*)vc)[i];
    }
}

__global__ void scatter_kernel(const int* __restrict__ tok) {
    int i = blockIdx.x * blockDim.x + threadIdx.x;
    const int tot4 = BB * SQ * (CC / 4);
    if (i >= tot4) return;
    int r  = i / (CC / 4);
    int c4 = (i % (CC / 4)) * 4;
    int b = r / SQ, s = r % SQ;
    int p = (s < TEXT_N) ? s : (TEXT_N + tok[s - TEXT_N]);
    size_t src = (size_t)r * N3C + CC + c4;
    size_t dst = ((size_t)b * SKV + p) * CC + c4;
    *(float4*)(g_kraw + dst) = *(const float4*)(g_qkv + src);
    *(float4*)(g_vraw + dst) = *(const float4*)(g_qkv + src + CC);
}

// ---------------- K: per-head LN + rope + transpose; V: transpose ----------------
__global__ __launch_bounds__(512) void kv_norm_kernel(const float* __restrict__ gk,
                                                      const float* __restrict__ bk,
                                                      const float* __restrict__ rc,
                                                      const float* __restrict__ rs) {
    const int bp = blockIdx.x;            // b * SKV + p
    const int b = bp / SKV, p = bp % SKV;
    const int w = threadIdx.x >> 5;       // head 0..15
    const int lid = threadIdx.x & 31;     // dims {2*lid, 2*lid+1}
    size_t base = (size_t)bp * CC + w * DD + 2 * lid;
    float2 x = *(const float2*)(g_kraw + base);
    float sum = x.x + x.y;
    float sq  = x.x * x.x + x.y * x.y;
#pragma unroll
    for (int off = 16; off; off >>= 1) {
        sum += __shfl_xor_sync(0xffffffffu, sum, off);
        sq  += __shfl_xor_sync(0xffffffffu, sq,  off);
    }
    float mean = sum * (1.0f / 64.0f);
    float var  = sq * (1.0f / 64.0f) - mean * mean;
    float rsig = rsqrtf(var + 1e-6f);
    float y0 = (x.x - mean) * rsig * gk[2*lid]   + bk[2*lid];
    float y1 = (x.y - mean) * rsig * gk[2*lid+1] + bk[2*lid+1];
    float o0 = y0, o1 = y1;
    if (p >= TEXT_N) {
        int rp = p - TEXT_N;
        float2 c  = *(const float2*)(rc + (size_t)rp * DD + 2 * lid);
        float2 sn = *(const float2*)(rs + (size_t)rp * DD + 2 * lid);
        o0 = y0 * c.x - y1 * sn.x;
        o1 = y1 * c.y + y0 * sn.y;
    }
    size_t ob = (((size_t)(b * HH + w)) * SKV + p) * DD + 2 * lid;
    *(float2*)(g_khead + ob) = make_float2(o0, o1);
    float2 v = *(const float2*)(g_vraw + base);
    *(float2*)(g_vhead + ob) = v;
}

// ---------------- Q: per-head LN + rope + transpose ----------------
__global__ __launch_bounds__(512) void q_norm_kernel(const float* __restrict__ gq,
                                                     const float* __restrict__ bq,
                                                     const float* __restrict__ rc,
                                                     const float* __restrict__ rs,
                                                     const int* __restrict__ tok) {
    const int bs = blockIdx.x;            // b * SQ + s
    const int b = bs / SQ, s = bs % SQ;
    const int w = threadIdx.x >> 5;
    const int lid = threadIdx.x & 31;
    size_t base = (size_t)bs * N3C + w * DD + 2 * lid;
    float2 x = *(const float2*)(g_qkv + base);
    float sum = x.x + x.y;
    float sq  = x.x * x.x + x.y * x.y;
#pragma unroll
    for (int off = 16; off; off >>= 1) {
        sum += __shfl_xor_sync(0xffffffffu, sum, off);
        sq  += __shfl_xor_sync(0xffffffffu, sq,  off);
    }
    float mean = sum * (1.0f / 64.0f);
    float var  = sq * (1.0f / 64.0f) - mean * mean;
    float rsig = rsqrtf(var + 1e-6f);
    float y0 = (x.x - mean) * rsig * gq[2*lid]   + bq[2*lid];
    float y1 = (x.y - mean) * rsig * gq[2*lid+1] + bq[2*lid+1];
    float o0 = y0, o1 = y1;
    if (s >= TEXT_N) {
        int rp = tok[s - TEXT_N];
        float2 c  = *(const float2*)(rc + (size_t)rp * DD + 2 * lid);
        float2 sn = *(const float2*)(rs + (size_t)rp * DD + 2 * lid);
        o0 = y0 * c.x - y1 * sn.x;
        o1 = y1 * c.y + y0 * sn.y;
    }
    size_t ob = (((size_t)(b * HH + w)) * SQ + s) * DD + 2 * lid;
    *(float2*)(g_qhead + ob) = make_float2(o0, o1);
}

// ---------------- flash attention: 1 q-row per thread ----------------
__global__ __launch_bounds__(128) void attn_kernel() {
    const int bh = blockIdx.x;            // b*H + h
    const int b = bh >> 4;
    const int h = bh & 15;
    const int qrow = blockIdx.y * 128 + threadIdx.x;
    const bool valid = qrow < SQ;
    __shared__ float Ks[64 * 64];
    __shared__ float Vs[64 * 64];
    float q[64], acc[64];
    float mval = -1e30f, lval = 0.f;
    {
        int qr = valid ? qrow : (SQ - 1);
        const float4* qp = (const float4*)(g_qhead + (((size_t)bh) * SQ + qr) * DD);
#pragma unroll
        for (int d4 = 0; d4 < 16; d4++) {
            float4 t = qp[d4];
            q[d4*4+0] = t.x * 0.125f; q[d4*4+1] = t.y * 0.125f;
            q[d4*4+2] = t.z * 0.125f; q[d4*4+3] = t.w * 0.125f;
        }
    }
#pragma unroll
    for (int d = 0; d < 64; d++) acc[d] = 0.f;

    const float4* kbase = (const float4*)(g_khead + (size_t)bh * SKV * DD);
    const float4* vbase = (const float4*)(g_vhead + (size_t)bh * SKV * DD);

    for (int kt = 0; kt < SKV; kt += 64) {
        int rows = min(64, SKV - kt);
        int n4 = rows * 16;
        float4* K4 = (float4*)Ks;
        float4* V4 = (float4*)Vs;
        for (int i = threadIdx.x; i < n4; i += 128) {
            K4[i] = kbase[kt * 16 + i];
            V4[i] = vbase[kt * 16 + i];
        }
        __syncthreads();
        if (valid) {
            for (int j = 0; j < rows; j++) {
                const float4* kr = (const float4*)(Ks + j * 64);
                float sp[4] = {0.f, 0.f, 0.f, 0.f};
#pragma unroll
                for (int d4 = 0; d4 < 16; d4++) {
                    float4 kv = kr[d4];
                    sp[d4 & 3] += q[d4*4+0]*kv.x + q[d4*4+1]*kv.y
                                + q[d4*4+2]*kv.z + q[d4*4+3]*kv.w;
                }
                float s = (sp[0] + sp[1]) + (sp[2] + sp[3]);
                if (s > mval) {
                    float corr = __expf(mval - s);
                    lval *= corr;
#pragma unroll
                    for (int d = 0; d < 64; d++) acc[d] *= corr;
                    mval = s;
                }
                float p = __expf(s - mval);
                lval += p;
                const float4* vr = (const float4*)(Vs + j * 64);
#pragma unroll
                for (int d4 = 0; d4 < 16; d4++) {
                    float4 vv = vr[d4];
                    acc[d4*4+0] += p * vv.x; acc[d4*4+1] += p * vv.y;
                    acc[d4*4+2] += p * vv.z; acc[d4*4+3] += p * vv.w;
                }
            }
        }
        __syncthreads();
    }

    if (valid) {
        float inv = 1.0f / lval;
        float4* op = (float4*)(g_attn + ((size_t)(b * SQ + qrow)) * CC + h * DD);
#pragma unroll
        for (int d4 = 0; d4 < 16; d4++) {
            float4 t;
            t.x = acc[d4*4+0] * inv; t.y = acc[d4*4+1] * inv;
            t.z = acc[d4*4+2] * inv; t.w = acc[d4*4+3] * inv;
            op[d4] = t;
        }
    }
}

// ---------------- out GEMM: attn @ Wo + bo, fused output reorder ----------------
__global__ __launch_bounds__(256) void gemm_out_kernel(const float* __restrict__ Wo,
                                                       const float* __restrict__ bo,
                                                       float* __restrict__ out) {
    const int M = BB * SQ;
    __shared__ float As[16][64];
    __shared__ float Bs[16][64];
    const int tid = threadIdx.x;
    const int m0 = blockIdx.y * 64;
    const int n0 = blockIdx.x * 64;
    const int arow  = tid >> 2;
    const int acol4 = (tid & 3) * 4;
    const int brow  = tid >> 4;
    const int bcol  = (tid & 15) * 4;
    const int ty = tid >> 4, tx = tid & 15;

    const float* asrc = (m0 + arow < M) ? (g_attn + (size_t)(m0 + arow) * CC) : nullptr;

    float cacc[4][4];
#pragma unroll
    for (int i = 0; i < 4; i++)
#pragma unroll
        for (int j = 0; j < 4; j++) cacc[i][j] = 0.f;

    for (int kk = 0; kk < CC; kk += 16) {
        float4 av = asrc ? *(const float4*)(asrc + kk + acol4) : make_float4(0,0,0,0);
        As[acol4+0][arow] = av.x; As[acol4+1][arow] = av.y;
        As[acol4+2][arow] = av.z; As[acol4+3][arow] = av.w;
        *(float4*)&Bs[brow][bcol] =
            *(const float4*)(Wo + (size_t)(kk + brow) * CC + n0 + bcol);
        __syncthreads();
#pragma unroll
        for (int k = 0; k < 16; k++) {
            float a[4], bv[4];
#pragma unroll
            for (int i = 0; i < 4; i++) a[i] = As[k][ty*4+i];
#pragma unroll
            for (int j = 0; j < 4; j++) bv[j] = Bs[k][tx*4+j];
#pragma unroll
            for (int i = 0; i < 4; i++)
#pragma unroll
                for (int j = 0; j < 4; j++) cacc[i][j] += a[i] * bv[j];
        }
        __syncthreads();
    }
    float4 bias = *(const float4*)(bo + n0 + tx*4);
#pragma unroll
    for (int i = 0; i < 4; i++) {
        int row = m0 + ty*4 + i;
        if (row < M) {
            int b = row / SQ, s = row % SQ;
            size_t off = (s >= TEXT_N)
                ? ((size_t)(b * NTOK_N + (s - TEXT_N))) * CC
                : (size_t)BB * NTOK_N * CC + ((size_t)(b * TEXT_N + s)) * CC;
            float4 t;
            t.x = cacc[i][0] + bias.x; t.y = cacc[i][1] + bias.y;
            t.z = cacc[i][2] + bias.z; t.w = cacc[i][3] + bias.w;
            *(float4*)(out + off + n0 + tx*4) = t;
        }
    }
}

// ---------------- launch ----------------
extern "C" void kernel_launch(void* const* d_in, const int* in_sizes, int n_in,
                              void* d_out, int out_size) {
    const float* hid = (const float*)d_in[0];
    const float* enc = (const float*)d_in[1];
    const float* Wq  = (const float*)d_in[2];
    const float* Wk  = (const float*)d_in[3];
    const float* Wv  = (const float*)d_in[4];
    const float* Wo  = (const float*)d_in[5];
    const float* bo  = (const float*)d_in[6];
    const float* gq  = (const float*)d_in[7];
    const float* bq  = (const float*)d_in[8];
    const float* gk  = (const float*)d_in[9];
    const float* bk  = (const float*)d_in[10];
    const float* rc  = (const float*)d_in[11];
    const float* rs  = (const float*)d_in[12];
    const float* kc  = (const float*)d_in[13];
    const float* vc  = (const float*)d_in[14];
    const int*   tok = (const int*)d_in[15];
    float* out = (float*)d_out;

    pack_w_kernel<<<(CC * N3C / 4 + 255) / 256, 256>>>(Wq, Wk, Wv);
    gemm_qkv_kernel<<<dim3(N3C / 64, (BB * SQ + 63) / 64), 256>>>(hid, enc);
    copy_cache_kernel<<<(BB * SKV * CC / 4 + 255) / 256, 256>>>(kc, vc);
    scatter_kernel<<<(BB * SQ * (CC / 4) + 255) / 256, 256>>>(tok);
    kv_norm_kernel<<<BB * SKV, 512>>>(gk, bk, rc, rs);
    q_norm_kernel<<<BB * SQ, 512>>>(gq, bq, rc, rs, tok);
    attn_kernel<<<dim3(BB * HH, (SQ + 127) / 128), 128>>>();
    gemm_out_kernel<<<dim3(CC / 64, (BB * SQ + 63) / 64), 256>>>(Wo, bo, out);
}

// round 3
// speedup vs baseline: 1.0022x; 1.0007x over previous
#include <cuda_runtime.h>
#include <math.h>

#define BB 2
#define HH 16
#define DD 64
#define CC 1024
#define TEXT_N 226
#define NTOK_N 1024
#define TOK_N 4096
#define SQ (TEXT_N + NTOK_N)   /* 1250 */
#define SKV (TEXT_N + TOK_N)   /* 4322 */
#define N3C (3*CC)             /* 3072 */

// ---------------- scratch (module-load allocated, allowed) ----------------
__device__ float g_wqkv [CC * N3C];            // packed [K=1024][N=3072]
__device__ float g_qkv  [BB * SQ * N3C];       // [2500, 3072] q|k|v
__device__ float g_kraw [BB * SKV * CC];       // scattered key cache
__device__ float g_vraw [BB * SKV * CC];       // scattered value cache
__device__ float g_khead[BB * HH * SKV * DD];  // LN+rope, [B,H,Skv,D]
__device__ float g_vhead[BB * HH * SKV * DD];  // [B,H,Skv,D]
__device__ float g_qhead[BB * HH * SQ * DD];   // LN+rope, [B,H,Sq,D]
__device__ float g_attn [BB * SQ * CC];        // attention out [B,Sq,C]

// ---------------- pack Wq|Wk|Wv -> [K, 3C] ----------------
__global__ void pack_w_kernel(const float* __restrict__ Wq,
                              const float* __restrict__ Wk,
                              const float* __restrict__ Wv) {
    int i = blockIdx.x * blockDim.x + threadIdx.x;
    const int tot4 = CC * N3C / 4;
    if (i >= tot4) return;
    int k = i / (N3C / 4);
    int n = (i % (N3C / 4)) * 4;
    const float* src = (n < CC)   ? (Wq + (size_t)k * CC + n)
                     : (n < 2*CC) ? (Wk + (size_t)k * CC + (n - CC))
                                  : (Wv + (size_t)k * CC + (n - 2*CC));
    ((float4*)g_wqkv)[i] = *(const float4*)src;
}

// ---------------- QKV GEMM: [2500,1024] @ [1024,3072] ----------------
__global__ __launch_bounds__(256) void gemm_qkv_kernel(const float* __restrict__ hid,
                                                       const float* __restrict__ enc) {
    const int M = BB * SQ;  // 2500
    __shared__ float As[16][64];
    __shared__ float Bs[16][64];
    const int tid = threadIdx.x;
    const int m0 = blockIdx.y * 64;
    const int n0 = blockIdx.x * 64;
    const int arow  = tid >> 2;
    const int acol4 = (tid & 3) * 4;
    const int brow  = tid >> 4;
    const int bcol  = (tid & 15) * 4;
    const int ty = tid >> 4, tx = tid & 15;

    const float* asrc = nullptr;
    {
        int grow = m0 + arow;
        if (grow < M) {
            int b = grow / SQ, s = grow % SQ;
            asrc = (s < TEXT_N) ? (enc + ((size_t)b * TEXT_N + s) * CC)
                                : (hid + ((size_t)b * NTOK_N + (s - TEXT_N)) * CC);
        }
    }
    float cacc[4][4];
#pragma unroll
    for (int i = 0; i < 4; i++)
#pragma unroll
        for (int j = 0; j < 4; j++) cacc[i][j] = 0.f;

    for (int kk = 0; kk < CC; kk += 16) {
        float4 av = asrc ? *(const float4*)(asrc + kk + acol4) : make_float4(0,0,0,0);
        As[acol4+0][arow] = av.x; As[acol4+1][arow] = av.y;
        As[acol4+2][arow] = av.z; As[acol4+3][arow] = av.w;
        *(float4*)&Bs[brow][bcol] =
            *(const float4*)(g_wqkv + (size_t)(kk + brow) * N3C + n0 + bcol);
        __syncthreads();
#pragma unroll
        for (int k = 0; k < 16; k++) {
            float a[4], bv[4];
#pragma unroll
            for (int i = 0; i < 4; i++) a[i] = As[k][ty*4+i];
#pragma unroll
            for (int j = 0; j < 4; j++) bv[j] = Bs[k][tx*4+j];
#pragma unroll
            for (int i = 0; i < 4; i++)
#pragma unroll
                for (int j = 0; j < 4; j++) cacc[i][j] += a[i] * bv[j];
        }
        __syncthreads();
    }
#pragma unroll
    for (int i = 0; i < 4; i++) {
        int row = m0 + ty*4 + i;
        if (row < M) {
            float4 t;
            t.x = cacc[i][0]; t.y = cacc[i][1]; t.z = cacc[i][2]; t.w = cacc[i][3];
            *(float4*)(g_qkv + (size_t)row * N3C + n0 + tx*4) = t;
        }
    }
}

// ---------------- cache copy + scatter of new K/V ----------------
__global__ void copy_cache_kernel(const float* __restrict__ kc,
                                  const float* __restrict__ vc) {
    int i = blockIdx.x * blockDim.x + threadIdx.x;
    const int tot4 = BB * SKV * CC / 4;
    if (i < tot4) {
        ((float4*)g_kraw)[i] = ((const float4*)kc)[i];
        ((float4*)g_vraw)[i] = ((const float4*)vc)[i];
    }
}

__global__ void scatter_kernel(const int* __restrict__ tok) {
    int i = blockIdx.x * blockDim.x + threadIdx.x;
    const int tot4 = BB * SQ * (CC / 4);
    if (i >= tot4) return;
    int r  = i / (CC / 4);
    int c4 = (i % (CC / 4)) * 4;
    int b = r / SQ, s = r % SQ;
    int p = (s < TEXT_N) ? s : (TEXT_N + tok[s - TEXT_N]);
    size_t src = (size_t)r * N3C + CC + c4;
    size_t dst = ((size_t)b * SKV + p) * CC + c4;
    *(float4*)(g_kraw + dst) = *(const float4*)(g_qkv + src);
    *(float4*)(g_vraw + dst) = *(const float4*)(g_qkv + src + CC);
}

// ---------------- K: per-head LN + rope + transpose; V: transpose ----------------
__global__ __launch_bounds__(512) void kv_norm_kernel(const float* __restrict__ gk,
                                                      const float* __restrict__ bk,
                                                      const float* __restrict__ rc,
                                                      const float* __restrict__ rs) {
    const int bp = blockIdx.x;            // b * SKV + p
    const int b = bp / SKV, p = bp % SKV;
    const int w = threadIdx.x >> 5;       // head 0..15
    const int lid = threadIdx.x & 31;     // dims {2*lid, 2*lid+1}
    size_t base = (size_t)bp * CC + w * DD + 2 * lid;
    float2 x = *(const float2*)(g_kraw + base);
    float sum = x.x + x.y;
    float sq  = x.x * x.x + x.y * x.y;
#pragma unroll
    for (int off = 16; off; off >>= 1) {
        sum += __shfl_xor_sync(0xffffffffu, sum, off);
        sq  += __shfl_xor_sync(0xffffffffu, sq,  off);
    }
    float mean = sum * (1.0f / 64.0f);
    float var  = sq * (1.0f / 64.0f) - mean * mean;
    float rsig = rsqrtf(var + 1e-6f);
    float y0 = (x.x - mean) * rsig * gk[2*lid]   + bk[2*lid];
    float y1 = (x.y - mean) * rsig * gk[2*lid+1] + bk[2*lid+1];
    float o0 = y0, o1 = y1;
    if (p >= TEXT_N) {
        int rp = p - TEXT_N;
        float2 c  = *(const float2*)(rc + (size_t)rp * DD + 2 * lid);
        float2 sn = *(const float2*)(rs + (size_t)rp * DD + 2 * lid);
        o0 = y0 * c.x - y1 * sn.x;
        o1 = y1 * c.y + y0 * sn.y;
    }
    size_t ob = (((size_t)(b * HH + w)) * SKV + p) * DD + 2 * lid;
    *(float2*)(g_khead + ob) = make_float2(o0, o1);
    float2 v = *(const float2*)(g_vraw + base);
    *(float2*)(g_vhead + ob) = v;
}

// ---------------- Q: per-head LN + rope + transpose ----------------
__global__ __launch_bounds__(512) void q_norm_kernel(const float* __restrict__ gq,
                                                     const float* __restrict__ bq,
                                                     const float* __restrict__ rc,
                                                     const float* __restrict__ rs,
                                                     const int* __restrict__ tok) {
    const int bs = blockIdx.x;            // b * SQ + s
    const int b = bs / SQ, s = bs % SQ;
    const int w = threadIdx.x >> 5;
    const int lid = threadIdx.x & 31;
    size_t base = (size_t)bs * N3C + w * DD + 2 * lid;
    float2 x = *(const float2*)(g_qkv + base);
    float sum = x.x + x.y;
    float sq  = x.x * x.x + x.y * x.y;
#pragma unroll
    for (int off = 16; off; off >>= 1) {
        sum += __shfl_xor_sync(0xffffffffu, sum, off);
        sq  += __shfl_xor_sync(0xffffffffu, sq,  off);
    }
    float mean = sum * (1.0f / 64.0f);
    float var  = sq * (1.0f / 64.0f) - mean * mean;
    float rsig = rsqrtf(var + 1e-6f);
    float y0 = (x.x - mean) * rsig * gq[2*lid]   + bq[2*lid];
    float y1 = (x.y - mean) * rsig * gq[2*lid+1] + bq[2*lid+1];
    float o0 = y0, o1 = y1;
    if (s >= TEXT_N) {
        int rp = tok[s - TEXT_N];
        float2 c  = *(const float2*)(rc + (size_t)rp * DD + 2 * lid);
        float2 sn = *(const float2*)(rs + (size_t)rp * DD + 2 * lid);
        o0 = y0 * c.x - y1 * sn.x;
        o1 = y1 * c.y + y0 * sn.y;
    }
    size_t ob = (((size_t)(b * HH + w)) * SQ + s) * DD + 2 * lid;
    *(float2*)(g_qhead + ob) = make_float2(o0, o1);
}

// ---------------- flash attention: 1 q-row per thread ----------------
__global__ __launch_bounds__(128) void attn_kernel() {
    const int bh = blockIdx.x;            // b*H + h
    const int b = bh >> 4;
    const int h = bh & 15;
    const int qrow = blockIdx.y * 128 + threadIdx.x;
    const bool valid = qrow < SQ;
    __shared__ float Ks[64 * 64];
    __shared__ float Vs[64 * 64];
    float q[64], acc[64];
    float mval = -1e30f, lval = 0.f;
    {
        int qr = valid ? qrow : (SQ - 1);
        const float4* qp = (const float4*)(g_qhead + (((size_t)bh) * SQ + qr) * DD);
#pragma unroll
        for (int d4 = 0; d4 < 16; d4++) {
            float4 t = qp[d4];
            q[d4*4+0] = t.x * 0.125f; q[d4*4+1] = t.y * 0.125f;
            q[d4*4+2] = t.z * 0.125f; q[d4*4+3] = t.w * 0.125f;
        }
    }
#pragma unroll
    for (int d = 0; d < 64; d++) acc[d] = 0.f;

    const float4* kbase = (const float4*)(g_khead + (size_t)bh * SKV * DD);
    const float4* vbase = (const float4*)(g_vhead + (size_t)bh * SKV * DD);

    for (int kt = 0; kt < SKV; kt += 64) {
        int rows = min(64, SKV - kt);
        int n4 = rows * 16;
        float4* K4 = (float4*)Ks;
        float4* V4 = (float4*)Vs;
        for (int i = threadIdx.x; i < n4; i += 128) {
            K4[i] = kbase[kt * 16 + i];
            V4[i] = vbase[kt * 16 + i];
        }
        __syncthreads();
        if (valid) {
            for (int j = 0; j < rows; j++) {
                const float4* kr = (const float4*)(Ks + j * 64);
                float sp[4] = {0.f, 0.f, 0.f, 0.f};
#pragma unroll
                for (int d4 = 0; d4 < 16; d4++) {
                    float4 kv = kr[d4];
                    sp[d4 & 3] += q[d4*4+0]*kv.x + q[d4*4+1]*kv.y
                                + q[d4*4+2]*kv.z + q[d4*4+3]*kv.w;
                }
                float s = (sp[0] + sp[1]) + (sp[2] + sp[3]);
                if (s > mval) {
                    float corr = __expf(mval - s);
                    lval *= corr;
#pragma unroll
                    for (int d = 0; d < 64; d++) acc[d] *= corr;
                    mval = s;
                }
                float p = __expf(s - mval);
                lval += p;
                const float4* vr = (const float4*)(Vs + j * 64);
#pragma unroll
                for (int d4 = 0; d4 < 16; d4++) {
                    float4 vv = vr[d4];
                    acc[d4*4+0] += p * vv.x; acc[d4*4+1] += p * vv.y;
                    acc[d4*4+2] += p * vv.z; acc[d4*4+3] += p * vv.w;
                }
            }
        }
        __syncthreads();
    }

    if (valid) {
        float inv = 1.0f / lval;
        float4* op = (float4*)(g_attn + ((size_t)(b * SQ + qrow)) * CC + h * DD);
#pragma unroll
        for (int d4 = 0; d4 < 16; d4++) {
            float4 t;
            t.x = acc[d4*4+0] * inv; t.y = acc[d4*4+1] * inv;
            t.z = acc[d4*4+2] * inv; t.w = acc[d4*4+3] * inv;
            op[d4] = t;
        }
    }
}

// ---------------- out GEMM: attn @ Wo + bo, fused output reorder ----------------
__global__ __launch_bounds__(256) void gemm_out_kernel(const float* __restrict__ Wo,
                                                       const float* __restrict__ bo,
                                                       float* __restrict__ out) {
    const int M = BB * SQ;
    __shared__ float As[16][64];
    __shared__ float Bs[16][64];
    const int tid = threadIdx.x;
    const int m0 = blockIdx.y * 64;
    const int n0 = blockIdx.x * 64;
    const int arow  = tid >> 2;
    const int acol4 = (tid & 3) * 4;
    const int brow  = tid >> 4;
    const int bcol  = (tid & 15) * 4;
    const int ty = tid >> 4, tx = tid & 15;

    const float* asrc = (m0 + arow < M) ? (g_attn + (size_t)(m0 + arow) * CC) : nullptr;

    float cacc[4][4];
#pragma unroll
    for (int i = 0; i < 4; i++)
#pragma unroll
        for (int j = 0; j < 4; j++) cacc[i][j] = 0.f;

    for (int kk = 0; kk < CC; kk += 16) {
        float4 av = asrc ? *(const float4*)(asrc + kk + acol4) : make_float4(0,0,0,0);
        As[acol4+0][arow] = av.x; As[acol4+1][arow] = av.y;
        As[acol4+2][arow] = av.z; As[acol4+3][arow] = av.w;
        *(float4*)&Bs[brow][bcol] =
            *(const float4*)(Wo + (size_t)(kk + brow) * CC + n0 + bcol);
        __syncthreads();
#pragma unroll
        for (int k = 0; k < 16; k++) {
            float a[4], bv[4];
#pragma unroll
            for (int i = 0; i < 4; i++) a[i] = As[k][ty*4+i];
#pragma unroll
            for (int j = 0; j < 4; j++) bv[j] = Bs[k][tx*4+j];
#pragma unroll
            for (int i = 0; i < 4; i++)
#pragma unroll
                for (int j = 0; j < 4; j++) cacc[i][j] += a[i] * bv[j];
        }
        __syncthreads();
    }
    float4 bias = *(const float4*)(bo + n0 + tx*4);
#pragma unroll
    for (int i = 0; i < 4; i++) {
        int row = m0 + ty*4 + i;
        if (row < M) {
            int b = row / SQ, s = row % SQ;
            size_t off = (s >= TEXT_N)
                ? ((size_t)(b * NTOK_N + (s - TEXT_N))) * CC
                : (size_t)BB * NTOK_N * CC + ((size_t)(b * TEXT_N + s)) * CC;
            float4 t;
            t.x = cacc[i][0] + bias.x; t.y = cacc[i][1] + bias.y;
            t.z = cacc[i][2] + bias.z; t.w = cacc[i][3] + bias.w;
            *(float4*)(out + off + n0 + tx*4) = t;
        }
    }
}

// ---------------- launch ----------------
extern "C" void kernel_launch(void* const* d_in, const int* in_sizes, int n_in,
                              void* d_out, int out_size) {
    const float* hid = (const float*)d_in[0];
    const float* enc = (const float*)d_in[1];
    const float* Wq  = (const float*)d_in[2];
    const float* Wk  = (const float*)d_in[3];
    const float* Wv  = (const float*)d_in[4];
    const float* Wo  = (const float*)d_in[5];
    const float* bo  = (const float*)d_in[6];
    const float* gq  = (const float*)d_in[7];
    const float* bq  = (const float*)d_in[8];
    const float* gk  = (const float*)d_in[9];
    const float* bk  = (const float*)d_in[10];
    const float* rc  = (const float*)d_in[11];
    const float* rs  = (const float*)d_in[12];
    const float* kc  = (const float*)d_in[13];
    const float* vc  = (const float*)d_in[14];
    const int*   tok = (const int*)d_in[15];
    float* out = (float*)d_out;

    pack_w_kernel<<<(CC * N3C / 4 + 255) / 256, 256>>>(Wq, Wk, Wv);
    gemm_qkv_kernel<<<dim3(N3C / 64, (BB * SQ + 63) / 64), 256>>>(hid, enc);
    copy_cache_kernel<<<(BB * SKV * CC / 4 + 255) / 256, 256>>>(kc, vc);
    scatter_kernel<<<(BB * SQ * (CC / 4) + 255) / 256, 256>>>(tok);
    kv_norm_kernel<<<BB * SKV, 512>>>(gk, bk, rc, rs);
    q_norm_kernel<<<BB * SQ, 512>>>(gq, bq, rc, rs, tok);
    attn_kernel<<<dim3(BB * HH, (SQ + 127) / 128), 128>>>();
    gemm_out_kernel<<<dim3(CC / 64, (BB * SQ + 63) / 64), 256>>>(Wo, bo, out);
}

// round 4
// speedup vs baseline: 2.9276x; 2.9213x over previous
#include <cuda_runtime.h>
#include <math.h>

#define BB 2
#define HH 16
#define DD 64
#define CC 1024
#define TEXT_N 226
#define NTOK_N 1024
#define TOK_N 4096
#define SQ (TEXT_N + NTOK_N)   /* 1250 */
#define SKV (TEXT_N + TOK_N)   /* 4322 */
#define N3C (3*CC)             /* 3072 */
#define SQP 1280               /* SQ padded to 64 */
#define SKVP 4352              /* SKV padded to 64 */

// ---------------- scratch ----------------
__device__ float g_wqkv  [CC * N3C];
__device__ float g_qkv   [BB * SQ * N3C];
__device__ float g_kraw  [BB * SKV * CC];
__device__ float g_vraw  [BB * SKV * CC];
__device__ float g_khead [BB * HH * SKVP * DD];   // [bh][skv_p][d], pad rows stay 0
__device__ float g_vheadT[BB * HH * DD * SKVP];   // [bh][d][skv_p]
__device__ float g_qhead [BB * HH * SQP * DD];    // [bh][sq_p][d]
__device__ float g_attn  [BB * SQ * CC];

// ---------------- helpers ----------------
__device__ __forceinline__ unsigned f2tf(float x) {
    unsigned r;
    asm("cvt.rna.tf32.f32 %0, %1;" : "=r"(r) : "f"(x));
    return r;
}

__device__ __forceinline__ void mma_tf32(float* c, const unsigned* a,
                                         unsigned b0, unsigned b1) {
    asm volatile(
        "mma.sync.aligned.m16n8k8.row.col.f32.tf32.tf32.f32 "
        "{%0,%1,%2,%3}, {%4,%5,%6,%7}, {%8,%9}, {%0,%1,%2,%3};"
        : "+f"(c[0]), "+f"(c[1]), "+f"(c[2]), "+f"(c[3])
        : "r"(a[0]), "r"(a[1]), "r"(a[2]), "r"(a[3]), "r"(b0), "r"(b1));
}

// ---------------- pack Wq|Wk|Wv -> [K, 3C] ----------------
__global__ void pack_w_kernel(const float* __restrict__ Wq,
                              const float* __restrict__ Wk,
                              const float* __restrict__ Wv) {
    int i = blockIdx.x * blockDim.x + threadIdx.x;
    const int tot4 = CC * N3C / 4;
    if (i >= tot4) return;
    int k = i / (N3C / 4);
    int n = (i % (N3C / 4)) * 4;
    const float* src = (n < CC)   ? (Wq + (size_t)k * CC + n)
                     : (n < 2*CC) ? (Wk + (size_t)k * CC + (n - CC))
                                  : (Wv + (size_t)k * CC + (n - 2*CC));
    ((float4*)g_wqkv)[i] = *(const float4*)src;
}

// ---------------- QKV GEMM (tf32 mma): [2500,1024]@[1024,3072] ----------------
#define ASTR 20
#define BSTR 136
__global__ __launch_bounds__(256) void gemm_qkv_mma(const float* __restrict__ hid,
                                                    const float* __restrict__ enc) {
    const int M = BB * SQ;
    __shared__ float As[128 * ASTR];
    __shared__ float Bs[16 * BSTR];
    const int tid = threadIdx.x;
    const int lane = tid & 31, wid = tid >> 5;
    const int g = lane >> 2, tig = lane & 3;
    const int wm = wid & 3, wn = wid >> 2;       // 4 x 2 warp grid
    const int m0 = blockIdx.y * 128;
    const int n0 = blockIdx.x * 128;

    // two fixed staging rows per thread
    int r1 = tid >> 2, c1 = (tid & 3) << 2;
    int r2 = (tid + 256) >> 2, c2 = ((tid + 256) & 3) << 2;
    const float* a1 = nullptr; const float* a2 = nullptr;
    {
        int gr = m0 + r1;
        if (gr < M) { int b = gr / SQ, s = gr % SQ;
            a1 = (s < TEXT_N) ? enc + ((size_t)b*TEXT_N+s)*CC : hid + ((size_t)b*NTOK_N+(s-TEXT_N))*CC; }
        gr = m0 + r2;
        if (gr < M) { int b = gr / SQ, s = gr % SQ;
            a2 = (s < TEXT_N) ? enc + ((size_t)b*TEXT_N+s)*CC : hid + ((size_t)b*NTOK_N+(s-TEXT_N))*CC; }
    }

    float cacc[2][8][4];
#pragma unroll
    for (int i = 0; i < 2; i++)
#pragma unroll
        for (int j = 0; j < 8; j++)
#pragma unroll
            for (int v = 0; v < 4; v++) cacc[i][j][v] = 0.f;

    for (int kk = 0; kk < CC; kk += 16) {
        {   // stage A (cvt to tf32)
            float4 v = a1 ? *(const float4*)(a1 + kk + c1) : make_float4(0,0,0,0);
            float* d = As + r1 * ASTR + c1;
            d[0]=__uint_as_float(f2tf(v.x)); d[1]=__uint_as_float(f2tf(v.y));
            d[2]=__uint_as_float(f2tf(v.z)); d[3]=__uint_as_float(f2tf(v.w));
            v = a2 ? *(const float4*)(a2 + kk + c2) : make_float4(0,0,0,0);
            d = As + r2 * ASTR + c2;
            d[0]=__uint_as_float(f2tf(v.x)); d[1]=__uint_as_float(f2tf(v.y));
            d[2]=__uint_as_float(f2tf(v.z)); d[3]=__uint_as_float(f2tf(v.w));
        }
        {   // stage B
#pragma unroll
            for (int i = tid; i < 512; i += 256) {
                int r = i >> 5, c4 = (i & 31) << 2;
                float4 v = *(const float4*)(g_wqkv + (size_t)(kk + r) * N3C + n0 + c4);
                float* d = Bs + r * BSTR + c4;
                d[0]=__uint_as_float(f2tf(v.x)); d[1]=__uint_as_float(f2tf(v.y));
                d[2]=__uint_as_float(f2tf(v.z)); d[3]=__uint_as_float(f2tf(v.w));
            }
        }
        __syncthreads();
#pragma unroll
        for (int ks = 0; ks < 2; ks++) {
            int k0 = ks * 8;
            unsigned af[2][4];
#pragma unroll
            for (int mf = 0; mf < 2; mf++) {
                int rb = wm * 32 + mf * 16 + g;
                af[mf][0] = __float_as_uint(As[rb * ASTR + k0 + tig]);
                af[mf][1] = __float_as_uint(As[(rb + 8) * ASTR + k0 + tig]);
                af[mf][2] = __float_as_uint(As[rb * ASTR + k0 + tig + 4]);
                af[mf][3] = __float_as_uint(As[(rb + 8) * ASTR + k0 + tig + 4]);
            }
#pragma unroll
            for (int nf = 0; nf < 8; nf++) {
                int nc = wn * 64 + nf * 8 + g;
                unsigned b0 = __float_as_uint(Bs[(k0 + tig) * BSTR + nc]);
                unsigned b1 = __float_as_uint(Bs[(k0 + tig + 4) * BSTR + nc]);
                mma_tf32(cacc[0][nf], af[0], b0, b1);
                mma_tf32(cacc[1][nf], af[1], b0, b1);
            }
        }
        __syncthreads();
    }
#pragma unroll
    for (int mf = 0; mf < 2; mf++) {
        int r0 = m0 + wm * 32 + mf * 16 + g;
#pragma unroll
        for (int nf = 0; nf < 8; nf++) {
            int col = n0 + wn * 64 + nf * 8 + 2 * tig;
            if (r0 < M)
                *(float2*)(g_qkv + (size_t)r0 * N3C + col) =
                    make_float2(cacc[mf][nf][0], cacc[mf][nf][1]);
            if (r0 + 8 < M)
                *(float2*)(g_qkv + (size_t)(r0 + 8) * N3C + col) =
                    make_float2(cacc[mf][nf][2], cacc[mf][nf][3]);
        }
    }
}

// ---------------- cache copy + scatter ----------------
__global__ void copy_cache_kernel(const float* __restrict__ kc,
                                  const float* __restrict__ vc) {
    int i = blockIdx.x * blockDim.x + threadIdx.x;
    const int tot4 = BB * SKV * CC / 4;
    if (i < tot4) {
        ((float4*)g_kraw)[i] = ((const float4*)kc)[i];
        ((float4*)g_vraw)[i] = ((const float4*)vc)[i];
    }
}

__global__ void scatter_kernel(const int* __restrict__ tok) {
    int i = blockIdx.x * blockDim.x + threadIdx.x;
    const int tot4 = BB * SQ * (CC / 4);
    if (i >= tot4) return;
    int r  = i / (CC / 4);
    int c4 = (i % (CC / 4)) * 4;
    int b = r / SQ, s = r % SQ;
    int p = (s < TEXT_N) ? s : (TEXT_N + tok[s - TEXT_N]);
    size_t src = (size_t)r * N3C + CC + c4;
    size_t dst = ((size_t)b * SKV + p) * CC + c4;
    *(float4*)(g_kraw + dst) = *(const float4*)(g_qkv + src);
    *(float4*)(g_vraw + dst) = *(const float4*)(g_qkv + src + CC);
}

// ---------------- K: LN+rope -> khead; V -> vheadT ----------------
__global__ __launch_bounds__(512) void kv_norm_kernel(const float* __restrict__ gk,
                                                      const float* __restrict__ bk,
                                                      const float* __restrict__ rc,
                                                      const float* __restrict__ rs) {
    const int bp = blockIdx.x;
    const int b = bp / SKV, p = bp % SKV;
    const int w = threadIdx.x >> 5;
    const int lid = threadIdx.x & 31;
    size_t base = (size_t)bp * CC + w * DD + 2 * lid;
    float2 x = *(const float2*)(g_kraw + base);
    float sum = x.x + x.y;
    float sq  = x.x * x.x + x.y * x.y;
#pragma unroll
    for (int off = 16; off; off >>= 1) {
        sum += __shfl_xor_sync(0xffffffffu, sum, off);
        sq  += __shfl_xor_sync(0xffffffffu, sq,  off);
    }
    float mean = sum * (1.0f / 64.0f);
    float var  = sq * (1.0f / 64.0f) - mean * mean;
    float rsig = rsqrtf(var + 1e-6f);
    float y0 = (x.x - mean) * rsig * gk[2*lid]   + bk[2*lid];
    float y1 = (x.y - mean) * rsig * gk[2*lid+1] + bk[2*lid+1];
    float o0 = y0, o1 = y1;
    if (p >= TEXT_N) {
        int rp = p - TEXT_N;
        float2 c  = *(const float2*)(rc + (size_t)rp * DD + 2 * lid);
        float2 sn = *(const float2*)(rs + (size_t)rp * DD + 2 * lid);
        o0 = y0 * c.x - y1 * sn.x;
        o1 = y1 * c.y + y0 * sn.y;
    }
    int bh = b * HH + w;
    *(float2*)(g_khead + ((size_t)bh * SKVP + p) * DD + 2 * lid) = make_float2(o0, o1);
    float2 v = *(const float2*)(g_vraw + base);
    size_t vb = ((size_t)bh * DD + 2 * lid) * SKVP + p;
    g_vheadT[vb]        = v.x;
    g_vheadT[vb + SKVP] = v.y;
}

// ---------------- Q: LN + rope -> qhead ----------------
__global__ __launch_bounds__(512) void q_norm_kernel(const float* __restrict__ gq,
                                                     const float* __restrict__ bq,
                                                     const float* __restrict__ rc,
                                                     const float* __restrict__ rs,
                                                     const int* __restrict__ tok) {
    const int bs = blockIdx.x;
    const int b = bs / SQ, s = bs % SQ;
    const int w = threadIdx.x >> 5;
    const int lid = threadIdx.x & 31;
    size_t base = (size_t)bs * N3C + w * DD + 2 * lid;
    float2 x = *(const float2*)(g_qkv + base);
    float sum = x.x + x.y;
    float sq  = x.x * x.x + x.y * x.y;
#pragma unroll
    for (int off = 16; off; off >>= 1) {
        sum += __shfl_xor_sync(0xffffffffu, sum, off);
        sq  += __shfl_xor_sync(0xffffffffu, sq,  off);
    }
    float mean = sum * (1.0f / 64.0f);
    float var  = sq * (1.0f / 64.0f) - mean * mean;
    float rsig = rsqrtf(var + 1e-6f);
    float y0 = (x.x - mean) * rsig * gq[2*lid]   + bq[2*lid];
    float y1 = (x.y - mean) * rsig * gq[2*lid+1] + bq[2*lid+1];
    float o0 = y0, o1 = y1;
    if (s >= TEXT_N) {
        int rp = tok[s - TEXT_N];
        float2 c  = *(const float2*)(rc + (size_t)rp * DD + 2 * lid);
        float2 sn = *(const float2*)(rs + (size_t)rp * DD + 2 * lid);
        o0 = y0 * c.x - y1 * sn.x;
        o1 = y1 * c.y + y0 * sn.y;
    }
    *(float2*)(g_qhead + ((size_t)(b * HH + w) * SQP + s) * DD + 2 * lid) = make_float2(o0, o1);
}

// ---------------- flash attention, tf32 mma, 64x64 tiles ----------------
#define TSTR 68
__global__ __launch_bounds__(128) void attn_mma_kernel() {
    extern __shared__ float sm[];
    float* Qs = sm;                 // 64 x 68 (reused as Ps)
    float* Ks = sm + 64 * TSTR;     // 64 x 68
    float* Vs = sm + 2 * 64 * TSTR; // 64(d) x 68(j)

    const int bh = blockIdx.x;
    const int b = bh >> 4, h = bh & 15;
    const int q0 = blockIdx.y * 64;
    const int tid = threadIdx.x;
    const int w = tid >> 5, lane = tid & 31;
    const int g = lane >> 2, tig = lane & 3;

    // stage Q (scaled, tf32)
    const float* qbase = g_qhead + ((size_t)bh * SQP + q0) * DD;
#pragma unroll
    for (int i = tid; i < 1024; i += 128) {
        int r = i >> 4, c4 = (i & 15) << 2;
        float4 v = *(const float4*)(qbase + r * DD + c4);
        float* d = Qs + r * TSTR + c4;
        d[0]=__uint_as_float(f2tf(v.x*0.125f)); d[1]=__uint_as_float(f2tf(v.y*0.125f));
        d[2]=__uint_as_float(f2tf(v.z*0.125f)); d[3]=__uint_as_float(f2tf(v.w*0.125f));
    }
    __syncthreads();

    unsigned qf[8][4];
    const int rb = w * 16 + g;
#pragma unroll
    for (int ks = 0; ks < 8; ks++) {
        int k0 = ks * 8;
        qf[ks][0] = __float_as_uint(Qs[rb * TSTR + k0 + tig]);
        qf[ks][1] = __float_as_uint(Qs[(rb + 8) * TSTR + k0 + tig]);
        qf[ks][2] = __float_as_uint(Qs[rb * TSTR + k0 + tig + 4]);
        qf[ks][3] = __float_as_uint(Qs[(rb + 8) * TSTR + k0 + tig + 4]);
    }
    __syncthreads();   // Qs now reusable as Ps

    float oacc[8][4];
#pragma unroll
    for (int nf = 0; nf < 8; nf++)
#pragma unroll
        for (int v = 0; v < 4; v++) oacc[nf][v] = 0.f;
    float m0 = -1e30f, m1 = -1e30f, l0 = 0.f, l1 = 0.f;

    const float* kbase  = g_khead  + (size_t)bh * SKVP * DD;
    const float* vtbase = g_vheadT + (size_t)bh * DD * SKVP;

    for (int kt = 0; kt < SKV; kt += 64) {
        // stage K tile (rows j, cols d) and Vt tile (rows d, cols j)
#pragma unroll
        for (int i = tid; i < 1024; i += 128) {
            int r = i >> 4, c4 = (i & 15) << 2;
            float4 v = *(const float4*)(kbase + (size_t)(kt + r) * DD + c4);
            float* d = Ks + r * TSTR + c4;
            d[0]=__uint_as_float(f2tf(v.x)); d[1]=__uint_as_float(f2tf(v.y));
            d[2]=__uint_as_float(f2tf(v.z)); d[3]=__uint_as_float(f2tf(v.w));
            v = *(const float4*)(vtbase + (size_t)r * SKVP + kt + c4);
            d = Vs + r * TSTR + c4;
            d[0]=__uint_as_float(f2tf(v.x)); d[1]=__uint_as_float(f2tf(v.y));
            d[2]=__uint_as_float(f2tf(v.z)); d[3]=__uint_as_float(f2tf(v.w));
        }
        __syncthreads();

        // S = Q K^T
        float sacc[8][4];
#pragma unroll
        for (int nf = 0; nf < 8; nf++)
#pragma unroll
            for (int v = 0; v < 4; v++) sacc[nf][v] = 0.f;
#pragma unroll
        for (int nf = 0; nf < 8; nf++) {
            int rn = (nf * 8 + g) * TSTR;
#pragma unroll
            for (int ks = 0; ks < 8; ks++) {
                unsigned b0 = __float_as_uint(Ks[rn + ks * 8 + tig]);
                unsigned b1 = __float_as_uint(Ks[rn + ks * 8 + tig + 4]);
                mma_tf32(sacc[nf], qf[ks], b0, b1);
            }
        }

        // mask tail columns
        if (kt + 64 > SKV) {
#pragma unroll
            for (int nf = 0; nf < 8; nf++) {
                int c = kt + nf * 8 + 2 * tig;
                if (c >= SKV)     { sacc[nf][0] = -1e30f; sacc[nf][2] = -1e30f; }
                if (c + 1 >= SKV) { sacc[nf][1] = -1e30f; sacc[nf][3] = -1e30f; }
            }
        }

        // online softmax (rows r0 = rb, r1 = rb+8)
        float tmax0 = -1e30f, tmax1 = -1e30f;
#pragma unroll
        for (int nf = 0; nf < 8; nf++) {
            tmax0 = fmaxf(tmax0, fmaxf(sacc[nf][0], sacc[nf][1]));
            tmax1 = fmaxf(tmax1, fmaxf(sacc[nf][2], sacc[nf][3]));
        }
        tmax0 = fmaxf(tmax0, __shfl_xor_sync(0xffffffffu, tmax0, 1));
        tmax0 = fmaxf(tmax0, __shfl_xor_sync(0xffffffffu, tmax0, 2));
        tmax1 = fmaxf(tmax1, __shfl_xor_sync(0xffffffffu, tmax1, 1));
        tmax1 = fmaxf(tmax1, __shfl_xor_sync(0xffffffffu, tmax1, 2));
        float mn0 = fmaxf(m0, tmax0), mn1 = fmaxf(m1, tmax1);
        float corr0 = __expf(m0 - mn0), corr1 = __expf(m1 - mn1);
        m0 = mn0; m1 = mn1;

        float tsum0 = 0.f, tsum1 = 0.f;
#pragma unroll
        for (int nf = 0; nf < 8; nf++) {
            float p00 = __expf(sacc[nf][0] - mn0);
            float p01 = __expf(sacc[nf][1] - mn0);
            float p10 = __expf(sacc[nf][2] - mn1);
            float p11 = __expf(sacc[nf][3] - mn1);
            tsum0 += p00 + p01; tsum1 += p10 + p11;
            int c = nf * 8 + 2 * tig;
            *(float2*)(Qs + rb * TSTR + c) =
                make_float2(__uint_as_float(f2tf(p00)), __uint_as_float(f2tf(p01)));
            *(float2*)(Qs + (rb + 8) * TSTR + c) =
                make_float2(__uint_as_float(f2tf(p10)), __uint_as_float(f2tf(p11)));
        }
        tsum0 += __shfl_xor_sync(0xffffffffu, tsum0, 1);
        tsum0 += __shfl_xor_sync(0xffffffffu, tsum0, 2);
        tsum1 += __shfl_xor_sync(0xffffffffu, tsum1, 1);
        tsum1 += __shfl_xor_sync(0xffffffffu, tsum1, 2);
        l0 = l0 * corr0 + tsum0;
        l1 = l1 * corr1 + tsum1;
#pragma unroll
        for (int nf = 0; nf < 8; nf++) {
            oacc[nf][0] *= corr0; oacc[nf][1] *= corr0;
            oacc[nf][2] *= corr1; oacc[nf][3] *= corr1;
        }
        __syncwarp();

        // O += P V  (A = P from Qs/Ps, B = Vt)
#pragma unroll
        for (int ks = 0; ks < 8; ks++) {
            int j0 = ks * 8;
            unsigned pf[4];
            pf[0] = __float_as_uint(Qs[rb * TSTR + j0 + tig]);
            pf[1] = __float_as_uint(Qs[(rb + 8) * TSTR + j0 + tig]);
            pf[2] = __float_as_uint(Qs[rb * TSTR + j0 + tig + 4]);
            pf[3] = __float_as_uint(Qs[(rb + 8) * TSTR + j0 + tig + 4]);
#pragma unroll
            for (int nf = 0; nf < 8; nf++) {
                int rn = (nf * 8 + g) * TSTR;
                unsigned b0 = __float_as_uint(Vs[rn + j0 + tig]);
                unsigned b1 = __float_as_uint(Vs[rn + j0 + tig + 4]);
                mma_tf32(oacc[nf], pf, b0, b1);
            }
        }
        __syncthreads();
    }

    // epilogue
    float inv0 = 1.0f / l0, inv1 = 1.0f / l1;
    int qr0 = q0 + rb, qr1 = qr0 + 8;
#pragma unroll
    for (int nf = 0; nf < 8; nf++) {
        int col = h * DD + nf * 8 + 2 * tig;
        if (qr0 < SQ)
            *(float2*)(g_attn + ((size_t)(b * SQ + qr0)) * CC + col) =
                make_float2(oacc[nf][0] * inv0, oacc[nf][1] * inv0);
        if (qr1 < SQ)
            *(float2*)(g_attn + ((size_t)(b * SQ + qr1)) * CC + col) =
                make_float2(oacc[nf][2] * inv1, oacc[nf][3] * inv1);
    }
}

// ---------------- out GEMM (tf32 mma) + bias + reorder ----------------
__global__ __launch_bounds__(256) void gemm_out_mma(const float* __restrict__ Wo,
                                                    const float* __restrict__ bo,
                                                    float* __restrict__ out) {
    const int M = BB * SQ;
    __shared__ float As[128 * ASTR];
    __shared__ float Bs[16 * BSTR];
    const int tid = threadIdx.x;
    const int lane = tid & 31, wid = tid >> 5;
    const int g = lane >> 2, tig = lane & 3;
    const int wm = wid & 3, wn = wid >> 2;
    const int m0 = blockIdx.y * 128;
    const int n0 = blockIdx.x * 128;

    int r1 = tid >> 2, c1 = (tid & 3) << 2;
    int r2 = (tid + 256) >> 2, c2 = ((tid + 256) & 3) << 2;
    const float* a1 = (m0 + r1 < M) ? g_attn + (size_t)(m0 + r1) * CC : nullptr;
    const float* a2 = (m0 + r2 < M) ? g_attn + (size_t)(m0 + r2) * CC : nullptr;

    float cacc[2][8][4];
#pragma unroll
    for (int i = 0; i < 2; i++)
#pragma unroll
        for (int j = 0; j < 8; j++)
#pragma unroll
            for (int v = 0; v < 4; v++) cacc[i][j][v] = 0.f;

    for (int kk = 0; kk < CC; kk += 16) {
        {
            float4 v = a1 ? *(const float4*)(a1 + kk + c1) : make_float4(0,0,0,0);
            float* d = As + r1 * ASTR + c1;
            d[0]=__uint_as_float(f2tf(v.x)); d[1]=__uint_as_float(f2tf(v.y));
            d[2]=__uint_as_float(f2tf(v.z)); d[3]=__uint_as_float(f2tf(v.w));
            v = a2 ? *(const float4*)(a2 + kk + c2) : make_float4(0,0,0,0);
            d = As + r2 * ASTR + c2;
            d[0]=__uint_as_float(f2tf(v.x)); d[1]=__uint_as_float(f2tf(v.y));
            d[2]=__uint_as_float(f2tf(v.z)); d[3]=__uint_as_float(f2tf(v.w));
        }
#pragma unroll
        for (int i = tid; i < 512; i += 256) {
            int r = i >> 5, c4 = (i & 31) << 2;
            float4 v = *(const float4*)(Wo + (size_t)(kk + r) * CC + n0 + c4);
            float* d = Bs + r * BSTR + c4;
            d[0]=__uint_as_float(f2tf(v.x)); d[1]=__uint_as_float(f2tf(v.y));
            d[2]=__uint_as_float(f2tf(v.z)); d[3]=__uint_as_float(f2tf(v.w));
        }
        __syncthreads();
#pragma unroll
        for (int ks = 0; ks < 2; ks++) {
            int k0 = ks * 8;
            unsigned af[2][4];
#pragma unroll
            for (int mf = 0; mf < 2; mf++) {
                int rbm = wm * 32 + mf * 16 + g;
                af[mf][0] = __float_as_uint(As[rbm * ASTR + k0 + tig]);
                af[mf][1] = __float_as_uint(As[(rbm + 8) * ASTR + k0 + tig]);
                af[mf][2] = __float_as_uint(As[rbm * ASTR + k0 + tig + 4]);
                af[mf][3] = __float_as_uint(As[(rbm + 8) * ASTR + k0 + tig + 4]);
            }
#pragma unroll
            for (int nf = 0; nf < 8; nf++) {
                int nc = wn * 64 + nf * 8 + g;
                unsigned b0 = __float_as_uint(Bs[(k0 + tig) * BSTR + nc]);
                unsigned b1 = __float_as_uint(Bs[(k0 + tig + 4) * BSTR + nc]);
                mma_tf32(cacc[0][nf], af[0], b0, b1);
                mma_tf32(cacc[1][nf], af[1], b0, b1);
            }
        }
        __syncthreads();
    }

#pragma unroll
    for (int mf = 0; mf < 2; mf++) {
#pragma unroll
        for (int half = 0; half < 2; half++) {
            int row = m0 + wm * 32 + mf * 16 + g + half * 8;
            if (row >= M) continue;
            int b = row / SQ, s = row % SQ;
            size_t off = (s >= TEXT_N)
                ? ((size_t)(b * NTOK_N + (s - TEXT_N))) * CC
                : (size_t)BB * NTOK_N * CC + ((size_t)(b * TEXT_N + s)) * CC;
#pragma unroll
            for (int nf = 0; nf < 8; nf++) {
                int col = n0 + wn * 64 + nf * 8 + 2 * tig;
                float2 t = make_float2(cacc[mf][nf][0 + 2*half] + bo[col],
                                       cacc[mf][nf][1 + 2*half] + bo[col + 1]);
                *(float2*)(out + off + col) = t;
            }
        }
    }
}

// ---------------- launch ----------------
extern "C" void kernel_launch(void* const* d_in, const int* in_sizes, int n_in,
                              void* d_out, int out_size) {
    const float* hid = (const float*)d_in[0];
    const float* enc = (const float*)d_in[1];
    const float* Wq  = (const float*)d_in[2];
    const float* Wk  = (const float*)d_in[3];
    const float* Wv  = (const float*)d_in[4];
    const float* Wo  = (const float*)d_in[5];
    const float* bo  = (const float*)d_in[6];
    const float* gq  = (const float*)d_in[7];
    const float* bq  = (const float*)d_in[8];
    const float* gk  = (const float*)d_in[9];
    const float* bk  = (const float*)d_in[10];
    const float* rc  = (const float*)d_in[11];
    const float* rs  = (const float*)d_in[12];
    const float* kc  = (const float*)d_in[13];
    const float* vc  = (const float*)d_in[14];
    const int*   tok = (const int*)d_in[15];
    float* out = (float*)d_out;

    const int attn_smem = 3 * 64 * TSTR * sizeof(float);   // 52224 B
    cudaFuncSetAttribute(attn_mma_kernel,
                         cudaFuncAttributeMaxDynamicSharedMemorySize, attn_smem);

    pack_w_kernel<<<(CC * N3C / 4 + 255) / 256, 256>>>(Wq, Wk, Wv);
    gemm_qkv_mma<<<dim3(N3C / 128, (BB * SQ + 127) / 128), 256>>>(hid, enc);
    copy_cache_kernel<<<(BB * SKV * CC / 4 + 255) / 256, 256>>>(kc, vc);
    scatter_kernel<<<(BB * SQ * (CC / 4) + 255) / 256, 256>>>(tok);
    kv_norm_kernel<<<BB * SKV, 512>>>(gk, bk, rc, rs);
    q_norm_kernel<<<BB * SQ, 512>>>(gq, bq, rc, rs, tok);
    attn_mma_kernel<<<dim3(BB * HH, (SQ + 63) / 64), 128, attn_smem>>>();
    gemm_out_mma<<<dim3(CC / 128, (BB * SQ + 127) / 128), 256>>>(Wo, bo, out);
}

// round 5
// speedup vs baseline: 3.2606x; 1.1137x over previous
#include <cuda_runtime.h>
#include <math.h>

#define BB 2
#define HH 16
#define DD 64
#define CC 1024
#define TEXT_N 226
#define NTOK_N 1024
#define TOK_N 4096
#define SQ (TEXT_N + NTOK_N)   /* 1250 */
#define SKV (TEXT_N + TOK_N)   /* 4322 */
#define N3C (3*CC)             /* 3072 */
#define SQP 1280               /* SQ padded to 128 */
#define SKVP 4352              /* SKV padded to 64 */
#define NKT 68                 /* SKVP/64 kv tiles */
#define KSPLIT 34              /* tiles per split */
#define NQT 10                 /* q tiles of 128 */

// ---------------- scratch (zero-initialized at module load) ----------------
__device__ float g_qkv   [BB * SQ * N3C];
__device__ float g_khead [BB * HH * SKVP * DD];   // [bh][skv_p][d], pad rows 0
__device__ float g_vheadT[BB * HH * DD * SKVP];   // [bh][d][skv_p], pad cols 0
__device__ float g_qhead [BB * HH * SQP * DD];    // [bh][sq_p][d], pad rows 0
__device__ float g_attn  [BB * SQ * CC];
__device__ int   g_inv   [TOK_N];
__device__ float g_ml    [2 * 32 * NQT * 128 * 2];   // [split][bhqt][row][m,l]
__device__ float g_op    [2 * 32 * NQT * 128 * 64];  // [split][bhqt][row][d]

// ---------------- helpers ----------------
__device__ __forceinline__ unsigned f2tf(float x) {
    unsigned r;
    asm("cvt.rna.tf32.f32 %0, %1;" : "=r"(r) : "f"(x));
    return r;
}
__device__ __forceinline__ float f2tff(float x) {
    return __uint_as_float(f2tf(x));
}
__device__ __forceinline__ void mma_tf32(float* c, const unsigned* a,
                                         unsigned b0, unsigned b1) {
    asm volatile(
        "mma.sync.aligned.m16n8k8.row.col.f32.tf32.tf32.f32 "
        "{%0,%1,%2,%3}, {%4,%5,%6,%7}, {%8,%9}, {%0,%1,%2,%3};"
        : "+f"(c[0]), "+f"(c[1]), "+f"(c[2]), "+f"(c[3])
        : "r"(a[0]), "r"(a[1]), "r"(a[2]), "r"(a[3]), "r"(b0), "r"(b1));
}
__device__ __forceinline__ void cp16(void* smem_dst, const void* gsrc) {
    unsigned sa = (unsigned)__cvta_generic_to_shared(smem_dst);
    asm volatile("cp.async.cg.shared.global [%0], [%1], 16;" :: "r"(sa), "l"(gsrc));
}
__device__ __forceinline__ void cp16z(void* smem_dst, const void* gsrc, bool pred) {
    unsigned sa = (unsigned)__cvta_generic_to_shared(smem_dst);
    int sz = pred ? 16 : 0;
    asm volatile("cp.async.cg.shared.global [%0], [%1], 16, %2;"
                 :: "r"(sa), "l"(gsrc), "r"(sz));
}
#define CP_COMMIT() asm volatile("cp.async.commit_group;")
#define CP_WAIT1()  asm volatile("cp.async.wait_group 1;")

// ---------------- inverse token map ----------------
__global__ void inv_init_kernel() {
    int i = blockIdx.x * blockDim.x + threadIdx.x;
    if (i < TOK_N) g_inv[i] = -1;
}
__global__ void inv_scatter_kernel(const int* __restrict__ tok) {
    int i = blockIdx.x * blockDim.x + threadIdx.x;
    if (i < NTOK_N) atomicMax(&g_inv[tok[i]], i);
}

// ---------------- GEMMs: 128x128 block, K-tile 32, cp.async double buffer ----
#define ASTR2 36
#define BSTR 136
#define GEMM_SMEM ((2*128*ASTR2 + 2*32*BSTR) * 4)   /* 71680 B */

__global__ __launch_bounds__(256) void gemm_qkv_mma(const float* __restrict__ hid,
                                                    const float* __restrict__ enc,
                                                    const float* __restrict__ Wq,
                                                    const float* __restrict__ Wk,
                                                    const float* __restrict__ Wv) {
    extern __shared__ float smg[];
    float* As = smg;
    float* Bs = smg + 2 * 128 * ASTR2;
    const int M = BB * SQ;
    const int tid = threadIdx.x;
    const int lane = tid & 31, wid = tid >> 5;
    const int g = lane >> 2, tig = lane & 3;
    const int wm = wid & 3, wn = wid >> 2;
    const int m0 = blockIdx.y * 128;
    const int n0 = blockIdx.x * 128;

    const float* wsrc = (n0 < CC)   ? (Wq + n0)
                      : (n0 < 2*CC) ? (Wk + n0 - CC)
                                    : (Wv + n0 - 2*CC);

    int ar[4], ac[4]; const float* ap[4]; bool av[4];
#pragma unroll
    for (int k = 0; k < 4; k++) {
        int i = tid + 256 * k;
        ar[k] = i >> 3; ac[k] = (i & 7) << 2;
        int gr = m0 + ar[k];
        av[k] = gr < M;
        ap[k] = enc;
        if (av[k]) {
            int b = gr / SQ, s = gr % SQ;
            ap[k] = (s < TEXT_N) ? enc + ((size_t)b*TEXT_N + s)*CC
                                 : hid + ((size_t)b*NTOK_N + (s - TEXT_N))*CC;
        }
    }

    auto stage = [&](int kk, int st) {
        float* dA = As + st * 128 * ASTR2;
        float* dB = Bs + st * 32 * BSTR;
#pragma unroll
        for (int k = 0; k < 4; k++)
            cp16z(dA + ar[k]*ASTR2 + ac[k], ap[k] + kk + ac[k], av[k]);
#pragma unroll
        for (int i = tid; i < 1024; i += 256) {
            int r = i >> 5, c4 = (i & 31) << 2;
            cp16(dB + r*BSTR + c4, wsrc + (size_t)(kk + r) * CC + c4);
        }
    };

    float cacc[2][8][4];
#pragma unroll
    for (int i = 0; i < 2; i++)
#pragma unroll
        for (int j = 0; j < 8; j++)
#pragma unroll
            for (int v = 0; v < 4; v++) cacc[i][j][v] = 0.f;

    stage(0, 0);
    CP_COMMIT();

    for (int t = 0; t < 32; t++) {
        int st = t & 1;
        if (t + 1 < 32) stage((t + 1) * 32, (t + 1) & 1);
        CP_COMMIT();
        CP_WAIT1();
        __syncthreads();
        float* pA = As + st * 128 * ASTR2;
        float* pB = Bs + st * 32 * BSTR;
        // in-place tf32 round
#pragma unroll
        for (int i = tid; i < 2048; i += 256) {
            float* p;
            if (i < 1024) { int r = i >> 3, c4 = (i & 7) << 2; p = pA + r*ASTR2 + c4; }
            else { int j = i - 1024; int r = j >> 5, c4 = (j & 31) << 2; p = pB + r*BSTR + c4; }
            float4 v = *(float4*)p;
            v.x = f2tff(v.x); v.y = f2tff(v.y); v.z = f2tff(v.z); v.w = f2tff(v.w);
            *(float4*)p = v;
        }
        __syncthreads();
#pragma unroll
        for (int ks2 = 0; ks2 < 4; ks2++) {
            const int k0 = ks2 * 8;
            unsigned af[2][4];
#pragma unroll
            for (int mf = 0; mf < 2; mf++) {
                int rbm = wm * 32 + mf * 16 + g;
                af[mf][0] = __float_as_uint(pA[rbm*ASTR2 + k0 + tig]);
                af[mf][1] = __float_as_uint(pA[(rbm+8)*ASTR2 + k0 + tig]);
                af[mf][2] = __float_as_uint(pA[rbm*ASTR2 + k0 + tig + 4]);
                af[mf][3] = __float_as_uint(pA[(rbm+8)*ASTR2 + k0 + tig + 4]);
            }
#pragma unroll
            for (int nf = 0; nf < 8; nf++) {
                int nc = wn * 64 + nf * 8 + g;
                unsigned b0 = __float_as_uint(pB[(k0+tig)*BSTR + nc]);
                unsigned b1 = __float_as_uint(pB[(k0+tig+4)*BSTR + nc]);
                mma_tf32(cacc[0][nf], af[0], b0, b1);
                mma_tf32(cacc[1][nf], af[1], b0, b1);
            }
        }
        __syncthreads();
    }

#pragma unroll
    for (int mf = 0; mf < 2; mf++) {
        int r0 = m0 + wm * 32 + mf * 16 + g;
#pragma unroll
        for (int nf = 0; nf < 8; nf++) {
            int col = n0 + wn * 64 + nf * 8 + 2 * tig;
            if (r0 < M)
                *(float2*)(g_qkv + (size_t)r0 * N3C + col) =
                    make_float2(cacc[mf][nf][0], cacc[mf][nf][1]);
            if (r0 + 8 < M)
                *(float2*)(g_qkv + (size_t)(r0 + 8) * N3C + col) =
                    make_float2(cacc[mf][nf][2], cacc[mf][nf][3]);
        }
    }
}

__global__ __launch_bounds__(256) void gemm_out_mma(const float* __restrict__ Wo,
                                                    const float* __restrict__ bo,
                                                    float* __restrict__ out) {
    extern __shared__ float smg[];
    float* As = smg;
    float* Bs = smg + 2 * 128 * ASTR2;
    const int M = BB * SQ;
    const int tid = threadIdx.x;
    const int lane = tid & 31, wid = tid >> 5;
    const int g = lane >> 2, tig = lane & 3;
    const int wm = wid & 3, wn = wid >> 2;
    const int m0 = blockIdx.y * 128;
    const int n0 = blockIdx.x * 128;
    const float* wsrc = Wo + n0;

    int ar[4], ac[4]; const float* ap[4]; bool av[4];
#pragma unroll
    for (int k = 0; k < 4; k++) {
        int i = tid + 256 * k;
        ar[k] = i >> 3; ac[k] = (i & 7) << 2;
        int gr = m0 + ar[k];
        av[k] = gr < M;
        ap[k] = g_attn + (size_t)(av[k] ? gr : 0) * CC;
    }

    auto stage = [&](int kk, int st) {
        float* dA = As + st * 128 * ASTR2;
        float* dB = Bs + st * 32 * BSTR;
#pragma unroll
        for (int k = 0; k < 4; k++)
            cp16z(dA + ar[k]*ASTR2 + ac[k], ap[k] + kk + ac[k], av[k]);
#pragma unroll
        for (int i = tid; i < 1024; i += 256) {
            int r = i >> 5, c4 = (i & 31) << 2;
            cp16(dB + r*BSTR + c4, wsrc + (size_t)(kk + r) * CC + c4);
        }
    };

    float cacc[2][8][4];
#pragma unroll
    for (int i = 0; i < 2; i++)
#pragma unroll
        for (int j = 0; j < 8; j++)
#pragma unroll
            for (int v = 0; v < 4; v++) cacc[i][j][v] = 0.f;

    stage(0, 0);
    CP_COMMIT();

    for (int t = 0; t < 32; t++) {
        int st = t & 1;
        if (t + 1 < 32) stage((t + 1) * 32, (t + 1) & 1);
        CP_COMMIT();
        CP_WAIT1();
        __syncthreads();
        float* pA = As + st * 128 * ASTR2;
        float* pB = Bs + st * 32 * BSTR;
#pragma unroll
        for (int i = tid; i < 2048; i += 256) {
            float* p;
            if (i < 1024) { int r = i >> 3, c4 = (i & 7) << 2; p = pA + r*ASTR2 + c4; }
            else { int j = i - 1024; int r = j >> 5, c4 = (j & 31) << 2; p = pB + r*BSTR + c4; }
            float4 v = *(float4*)p;
            v.x = f2tff(v.x); v.y = f2tff(v.y); v.z = f2tff(v.z); v.w = f2tff(v.w);
            *(float4*)p = v;
        }
        __syncthreads();
#pragma unroll
        for (int ks2 = 0; ks2 < 4; ks2++) {
            const int k0 = ks2 * 8;
            unsigned af[2][4];
#pragma unroll
            for (int mf = 0; mf < 2; mf++) {
                int rbm = wm * 32 + mf * 16 + g;
                af[mf][0] = __float_as_uint(pA[rbm*ASTR2 + k0 + tig]);
                af[mf][1] = __float_as_uint(pA[(rbm+8)*ASTR2 + k0 + tig]);
                af[mf][2] = __float_as_uint(pA[rbm*ASTR2 + k0 + tig + 4]);
                af[mf][3] = __float_as_uint(pA[(rbm+8)*ASTR2 + k0 + tig + 4]);
            }
#pragma unroll
            for (int nf = 0; nf < 8; nf++) {
                int nc = wn * 64 + nf * 8 + g;
                unsigned b0 = __float_as_uint(pB[(k0+tig)*BSTR + nc]);
                unsigned b1 = __float_as_uint(pB[(k0+tig+4)*BSTR + nc]);
                mma_tf32(cacc[0][nf], af[0], b0, b1);
                mma_tf32(cacc[1][nf], af[1], b0, b1);
            }
        }
        __syncthreads();
    }

#pragma unroll
    for (int mf = 0; mf < 2; mf++) {
#pragma unroll
        for (int half = 0; half < 2; half++) {
            int row = m0 + wm * 32 + mf * 16 + g + half * 8;
            if (row >= M) continue;
            int b = row / SQ, s = row % SQ;
            size_t off = (s >= TEXT_N)
                ? ((size_t)(b * NTOK_N + (s - TEXT_N))) * CC
                : (size_t)BB * NTOK_N * CC + ((size_t)(b * TEXT_N + s)) * CC;
#pragma unroll
            for (int nf = 0; nf < 8; nf++) {
                int col = n0 + wn * 64 + nf * 8 + 2 * tig;
                float2 t = make_float2(cacc[mf][nf][0 + 2*half] + bo[col],
                                       cacc[mf][nf][1 + 2*half] + bo[col + 1]);
                *(float2*)(out + off + col) = t;
            }
        }
    }
}

// ---------------- fused K/V: gather + LN + rope + transpose ----------------
__global__ __launch_bounds__(512) void kv_norm_kernel(const float* __restrict__ gk,
                                                      const float* __restrict__ bk,
                                                      const float* __restrict__ rc,
                                                      const float* __restrict__ rs,
                                                      const float* __restrict__ kc,
                                                      const float* __restrict__ vc) {
    const int bp = blockIdx.x;
    const int b = bp / SKV, p = bp % SKV;
    const int w = threadIdx.x >> 5;
    const int lid = threadIdx.x & 31;
    const float* ksrc; const float* vsrc;
    if (p < TEXT_N) {
        size_t row = ((size_t)(b * SQ + p)) * N3C;
        ksrc = g_qkv + row + CC; vsrc = g_qkv + row + 2*CC;
    } else {
        int i = g_inv[p - TEXT_N];
        if (i >= 0) {
            size_t row = ((size_t)(b * SQ + TEXT_N + i)) * N3C;
            ksrc = g_qkv + row + CC; vsrc = g_qkv + row + 2*CC;
        } else {
            size_t row = ((size_t)(b * SKV + p)) * CC;
            ksrc = kc + row; vsrc = vc + row;
        }
    }
    float2 x = *(const float2*)(ksrc + w * DD + 2 * lid);
    float sum = x.x + x.y;
    float sq  = x.x * x.x + x.y * x.y;
#pragma unroll
    for (int off = 16; off; off >>= 1) {
        sum += __shfl_xor_sync(0xffffffffu, sum, off);
        sq  += __shfl_xor_sync(0xffffffffu, sq,  off);
    }
    float mean = sum * (1.0f / 64.0f);
    float var  = sq * (1.0f / 64.0f) - mean * mean;
    float rsig = rsqrtf(var + 1e-6f);
    float y0 = (x.x - mean) * rsig * gk[2*lid]   + bk[2*lid];
    float y1 = (x.y - mean) * rsig * gk[2*lid+1] + bk[2*lid+1];
    float o0 = y0, o1 = y1;
    if (p >= TEXT_N) {
        int rp = p - TEXT_N;
        float2 c  = *(const float2*)(rc + (size_t)rp * DD + 2 * lid);
        float2 sn = *(const float2*)(rs + (size_t)rp * DD + 2 * lid);
        o0 = y0 * c.x - y1 * sn.x;
        o1 = y1 * c.y + y0 * sn.y;
    }
    int bh = b * HH + w;
    *(float2*)(g_khead + ((size_t)bh * SKVP + p) * DD + 2 * lid) = make_float2(o0, o1);
    float2 v = *(const float2*)(vsrc + w * DD + 2 * lid);
    size_t vb = ((size_t)bh * DD + 2 * lid) * SKVP + p;
    g_vheadT[vb]        = v.x;
    g_vheadT[vb + SKVP] = v.y;
}

// ---------------- Q: LN + rope ----------------
__global__ __launch_bounds__(512) void q_norm_kernel(const float* __restrict__ gq,
                                                     const float* __restrict__ bq,
                                                     const float* __restrict__ rc,
                                                     const float* __restrict__ rs,
                                                     const int* __restrict__ tok) {
    const int bs = blockIdx.x;
    const int b = bs / SQ, s = bs % SQ;
    const int w = threadIdx.x >> 5;
    const int lid = threadIdx.x & 31;
    size_t base = (size_t)bs * N3C + w * DD + 2 * lid;
    float2 x = *(const float2*)(g_qkv + base);
    float sum = x.x + x.y;
    float sq  = x.x * x.x + x.y * x.y;
#pragma unroll
    for (int off = 16; off; off >>= 1) {
        sum += __shfl_xor_sync(0xffffffffu, sum, off);
        sq  += __shfl_xor_sync(0xffffffffu, sq,  off);
    }
    float mean = sum * (1.0f / 64.0f);
    float var  = sq * (1.0f / 64.0f) - mean * mean;
    float rsig = rsqrtf(var + 1e-6f);
    float y0 = (x.x - mean) * rsig * gq[2*lid]   + bq[2*lid];
    float y1 = (x.y - mean) * rsig * gq[2*lid+1] + bq[2*lid+1];
    float o0 = y0, o1 = y1;
    if (s >= TEXT_N) {
        int rp = tok[s - TEXT_N];
        float2 c  = *(const float2*)(rc + (size_t)rp * DD + 2 * lid);
        float2 sn = *(const float2*)(rs + (size_t)rp * DD + 2 * lid);
        o0 = y0 * c.x - y1 * sn.x;
        o1 = y1 * c.y + y0 * sn.y;
    }
    *(float2*)(g_qhead + ((size_t)(b * HH + w) * SQP + s) * DD + 2 * lid) = make_float2(o0, o1);
}

// ---------------- flash attention: 128-row q tiles, split-KV x2 ----------------
#define TSTR 68
#define ATTN_SMEM_USED ((4*64*TSTR + 128*TSTR) * 4)   /* 104448 B */
#define ATTN_SMEM 120000                              /* force 1 CTA/SM */

__global__ __launch_bounds__(256) void attn_mma_kernel() {
    extern __shared__ float sm[];
    float* Ps = sm + 4 * 64 * TSTR;   // 128 x TSTR (Q staging, then P)

    const int bh = blockIdx.x;
    const int qt = blockIdx.y;
    const int split = blockIdx.z;
    const int q0 = qt * 128;
    const int tid = threadIdx.x;
    const int w = tid >> 5, lane = tid & 31;
    const int g = lane >> 2, tig = lane & 3;
    const int rb = w * 16 + g;

    const float* kbase  = g_khead  + (size_t)bh * SKVP * DD;
    const float* vtbase = g_vheadT + (size_t)bh * DD * SKVP;

    // stage Q (scaled, tf32) and extract fragments
    const float* qbase = g_qhead + ((size_t)bh * SQP + q0) * DD;
#pragma unroll
    for (int i = tid; i < 2048; i += 256) {
        int r = i >> 4, c4 = (i & 15) << 2;
        float4 v = *(const float4*)(qbase + r * DD + c4);
        float* d = Ps + r * TSTR + c4;
        d[0] = f2tff(v.x * 0.125f); d[1] = f2tff(v.y * 0.125f);
        d[2] = f2tff(v.z * 0.125f); d[3] = f2tff(v.w * 0.125f);
    }
    __syncthreads();
    unsigned qf[8][4];
#pragma unroll
    for (int ks = 0; ks < 8; ks++) {
        int k0 = ks * 8;
        qf[ks][0] = __float_as_uint(Ps[rb * TSTR + k0 + tig]);
        qf[ks][1] = __float_as_uint(Ps[(rb + 8) * TSTR + k0 + tig]);
        qf[ks][2] = __float_as_uint(Ps[rb * TSTR + k0 + tig + 4]);
        qf[ks][3] = __float_as_uint(Ps[(rb + 8) * TSTR + k0 + tig + 4]);
    }
    __syncthreads();   // Ps now reusable as P buffer

    float oacc[8][4];
#pragma unroll
    for (int nf = 0; nf < 8; nf++)
#pragma unroll
        for (int v = 0; v < 4; v++) oacc[nf][v] = 0.f;
    float mx0 = -1e30f, mx1 = -1e30f, l0 = 0.f, l1 = 0.f;

    const int t0 = split * KSPLIT, t1 = t0 + KSPLIT;

    auto stage_kv = [&](float* dst, int kt) {
#pragma unroll
        for (int i = tid; i < 2048; i += 256) {
            int half = i >> 10, j = i & 1023;
            int r = j >> 4, c4 = (j & 15) << 2;
            const float* src = half ? (vtbase + (size_t)r * SKVP + kt + c4)
                                    : (kbase + (size_t)(kt + r) * DD + c4);
            cp16(dst + half * 64 * TSTR + r * TSTR + c4, src);
        }
    };

    stage_kv(sm, t0 * 64);
    CP_COMMIT();

    for (int t = t0; t < t1; t++) {
        int st = (t - t0) & 1;
        if (t + 1 < t1) stage_kv(sm + ((t + 1 - t0) & 1) * (2 * 64 * TSTR), (t + 1) * 64);
        CP_COMMIT();
        CP_WAIT1();
        __syncthreads();
        float* Ks = sm + st * (2 * 64 * TSTR);
        float* Vs = Ks + 64 * TSTR;
        // in-place tf32 round of K and V tiles
#pragma unroll
        for (int i = tid; i < 2048; i += 256) {
            int half = i >> 10, j = i & 1023;
            int r = j >> 4, c4 = (j & 15) << 2;
            float* p = Ks + half * 64 * TSTR + r * TSTR + c4;
            float4 v = *(float4*)p;
            v.x = f2tff(v.x); v.y = f2tff(v.y); v.z = f2tff(v.z); v.w = f2tff(v.w);
            *(float4*)p = v;
        }
        __syncthreads();

        const int kt = t * 64;

        // S = Q K^T
        float sacc[8][4];
#pragma unroll
        for (int nf = 0; nf < 8; nf++)
#pragma unroll
            for (int v = 0; v < 4; v++) sacc[nf][v] = 0.f;
#pragma unroll
        for (int nf = 0; nf < 8; nf++) {
            int rn = (nf * 8 + g) * TSTR;
#pragma unroll
            for (int ks = 0; ks < 8; ks++) {
                unsigned b0 = __float_as_uint(Ks[rn + ks * 8 + tig]);
                unsigned b1 = __float_as_uint(Ks[rn + ks * 8 + tig + 4]);
                mma_tf32(sacc[nf], qf[ks], b0, b1);
            }
        }

        // mask tail columns
        if (kt + 64 > SKV) {
#pragma unroll
            for (int nf = 0; nf < 8; nf++) {
                int c = kt + nf * 8 + 2 * tig;
                if (c >= SKV)     { sacc[nf][0] = -1e30f; sacc[nf][2] = -1e30f; }
                if (c + 1 >= SKV) { sacc[nf][1] = -1e30f; sacc[nf][3] = -1e30f; }
            }
        }

        // online softmax (rows rb, rb+8)
        float tmax0 = -1e30f, tmax1 = -1e30f;
#pragma unroll
        for (int nf = 0; nf < 8; nf++) {
            tmax0 = fmaxf(tmax0, fmaxf(sacc[nf][0], sacc[nf][1]));
            tmax1 = fmaxf(tmax1, fmaxf(sacc[nf][2], sacc[nf][3]));
        }
        tmax0 = fmaxf(tmax0, __shfl_xor_sync(0xffffffffu, tmax0, 1));
        tmax0 = fmaxf(tmax0, __shfl_xor_sync(0xffffffffu, tmax0, 2));
        tmax1 = fmaxf(tmax1, __shfl_xor_sync(0xffffffffu, tmax1, 1));
        tmax1 = fmaxf(tmax1, __shfl_xor_sync(0xffffffffu, tmax1, 2));
        float mn0 = fmaxf(mx0, tmax0), mn1 = fmaxf(mx1, tmax1);
        float corr0 = __expf(mx0 - mn0), corr1 = __expf(mx1 - mn1);
        mx0 = mn0; mx1 = mn1;

        float tsum0 = 0.f, tsum1 = 0.f;
#pragma unroll
        for (int nf = 0; nf < 8; nf++) {
            float p00 = __expf(sacc[nf][0] - mn0);
            float p01 = __expf(sacc[nf][1] - mn0);
            float p10 = __expf(sacc[nf][2] - mn1);
            float p11 = __expf(sacc[nf][3] - mn1);
            tsum0 += p00 + p01; tsum1 += p10 + p11;
            int c = nf * 8 + 2 * tig;
            *(float2*)(Ps + rb * TSTR + c) = make_float2(f2tff(p00), f2tff(p01));
            *(float2*)(Ps + (rb + 8) * TSTR + c) = make_float2(f2tff(p10), f2tff(p11));
        }
        tsum0 += __shfl_xor_sync(0xffffffffu, tsum0, 1);
        tsum0 += __shfl_xor_sync(0xffffffffu, tsum0, 2);
        tsum1 += __shfl_xor_sync(0xffffffffu, tsum1, 1);
        tsum1 += __shfl_xor_sync(0xffffffffu, tsum1, 2);
        l0 = l0 * corr0 + tsum0;
        l1 = l1 * corr1 + tsum1;
#pragma unroll
        for (int nf = 0; nf < 8; nf++) {
            oacc[nf][0] *= corr0; oacc[nf][1] *= corr0;
            oacc[nf][2] *= corr1; oacc[nf][3] *= corr1;
        }
        __syncwarp();

        // O += P V
#pragma unroll
        for (int ks = 0; ks < 8; ks++) {
            int j0 = ks * 8;
            unsigned pf[4];
            pf[0] = __float_as_uint(Ps[rb * TSTR + j0 + tig]);
            pf[1] = __float_as_uint(Ps[(rb + 8) * TSTR + j0 + tig]);
            pf[2] = __float_as_uint(Ps[rb * TSTR + j0 + tig + 4]);
            pf[3] = __float_as_uint(Ps[(rb + 8) * TSTR + j0 + tig + 4]);
#pragma unroll
            for (int nf = 0; nf < 8; nf++) {
                int rn = (nf * 8 + g) * TSTR;
                unsigned b0 = __float_as_uint(Vs[rn + j0 + tig]);
                unsigned b1 = __float_as_uint(Vs[rn + j0 + tig + 4]);
                mma_tf32(oacc[nf], pf, b0, b1);
            }
        }
        __syncthreads();
    }

    // split epilogue: unnormalized O + (m, l)
    const int bhqt = bh * NQT + qt;
    const size_t obase = ((size_t)(split * 32 * NQT + bhqt)) * 128 * 64;
#pragma unroll
    for (int nf = 0; nf < 8; nf++) {
        int col = nf * 8 + 2 * tig;
        *(float2*)(g_op + obase + (size_t)rb * 64 + col) =
            make_float2(oacc[nf][0], oacc[nf][1]);
        *(float2*)(g_op + obase + (size_t)(rb + 8) * 64 + col) =
            make_float2(oacc[nf][2], oacc[nf][3]);
    }
    if (tig == 0) {
        size_t mb = ((size_t)(split * 32 * NQT + bhqt)) * 128 * 2;
        g_ml[mb + rb * 2]       = mx0;
        g_ml[mb + rb * 2 + 1]   = l0;
        g_ml[mb + (rb + 8) * 2]     = mx1;
        g_ml[mb + (rb + 8) * 2 + 1] = l1;
    }
}

// ---------------- merge the two KV splits ----------------
__global__ void attn_merge_kernel() {
    int idx = blockIdx.x * blockDim.x + threadIdx.x;
    const int total = 32 * NQT * 128 * 32;
    if (idx >= total) return;
    int lane = idx & 31;
    int row = idx >> 5;                 // bhqt*128 + r
    int r = row & 127;
    int bhqt = row >> 7;
    int qt = bhqt % NQT, bh = bhqt / NQT;
    int qr = qt * 128 + r;
    if (qr >= SQ) return;
    size_t mb0 = (size_t)bhqt * 256 + r * 2;
    size_t mb1 = (size_t)(32 * NQT + bhqt) * 256 + r * 2;
    float m0 = g_ml[mb0], la = g_ml[mb0 + 1];
    float m1 = g_ml[mb1], lb = g_ml[mb1 + 1];
    float m = fmaxf(m0, m1);
    float c0 = __expf(m0 - m), c1 = __expf(m1 - m);
    float inv = 1.0f / (la * c0 + lb * c1);
    float2 a = *(const float2*)(g_op + ((size_t)bhqt * 128 + r) * 64 + 2 * lane);
    float2 bv = *(const float2*)(g_op + ((size_t)(32 * NQT + bhqt) * 128 + r) * 64 + 2 * lane);
    int b = bh >> 4, h = bh & 15;
    *(float2*)(g_attn + ((size_t)(b * SQ + qr)) * CC + h * DD + 2 * lane) =
        make_float2((a.x * c0 + bv.x * c1) * inv, (a.y * c0 + bv.y * c1) * inv);
}

// ---------------- launch ----------------
extern "C" void kernel_launch(void* const* d_in, const int* in_sizes, int n_in,
                              void* d_out, int out_size) {
    const float* hid = (const float*)d_in[0];
    const float* enc = (const float*)d_in[1];
    const float* Wq  = (const float*)d_in[2];
    const float* Wk  = (const float*)d_in[3];
    const float* Wv  = (const float*)d_in[4];
    const float* Wo  = (const float*)d_in[5];
    const float* bo  = (const float*)d_in[6];
    const float* gq  = (const float*)d_in[7];
    const float* bq  = (const float*)d_in[8];
    const float* gk  = (const float*)d_in[9];
    const float* bk  = (const float*)d_in[10];
    const float* rc  = (const float*)d_in[11];
    const float* rs  = (const float*)d_in[12];
    const float* kc  = (const float*)d_in[13];
    const float* vc  = (const float*)d_in[14];
    const int*   tok = (const int*)d_in[15];
    float* out = (float*)d_out;

    cudaFuncSetAttribute(gemm_qkv_mma,
                         cudaFuncAttributeMaxDynamicSharedMemorySize, GEMM_SMEM);
    cudaFuncSetAttribute(gemm_out_mma,
                         cudaFuncAttributeMaxDynamicSharedMemorySize, GEMM_SMEM);
    cudaFuncSetAttribute(attn_mma_kernel,
                         cudaFuncAttributeMaxDynamicSharedMemorySize, ATTN_SMEM);

    inv_init_kernel<<<(TOK_N + 255) / 256, 256>>>();
    inv_scatter_kernel<<<(NTOK_N + 255) / 256, 256>>>(tok);
    gemm_qkv_mma<<<dim3(N3C / 128, (BB * SQ + 127) / 128), 256, GEMM_SMEM>>>(
        hid, enc, Wq, Wk, Wv);
    kv_norm_kernel<<<BB * SKV, 512>>>(gk, bk, rc, rs, kc, vc);
    q_norm_kernel<<<BB * SQ, 512>>>(gq, bq, rc, rs, tok);
    attn_mma_kernel<<<dim3(BB * HH, NQT, 2), 256, ATTN_SMEM>>>();
    attn_merge_kernel<<<(32 * NQT * 128 * 32 + 255) / 256, 256>>>();
    gemm_out_mma<<<dim3(CC / 128, (BB * SQ + 127) / 128), 256, GEMM_SMEM>>>(Wo, bo, out);
}

// round 6
// speedup vs baseline: 4.5408x; 1.3927x over previous
#include <cuda_runtime.h>
#include <math.h>

#define BB 2
#define HH 16
#define DD 64
#define CC 1024
#define TEXT_N 226
#define NTOK_N 1024
#define TOK_N 4096
#define SQ (TEXT_N + NTOK_N)   /* 1250 */
#define SKV (TEXT_N + TOK_N)   /* 4322 */
#define N3C (3*CC)             /* 3072 */
#define SQP 1280               /* SQ padded to 128 */
#define SKVP 4352              /* SKV padded to 64 */
#define NKT 68                 /* SKVP/64 kv tiles */
#define KSPLIT 34              /* tiles per split */
#define NQT 10                 /* q tiles of 128 */
#define MM (BB * SQ)           /* 2500 */

// ---------------- scratch (zero-initialized at module load) ----------------
__device__ float g_h     [MM * CC];               // rounded enc|hid rows
__device__ float g_wqkv  [CC * N3C];              // rounded packed weights
__device__ float g_wo    [CC * CC];               // rounded Wo
__device__ float g_qkv   [MM * N3C];
__device__ float g_khead [BB * HH * SKVP * DD];   // rounded, pad rows 0
__device__ float g_vhead [BB * HH * SKVP * DD];   // rounded, natural layout
__device__ float g_qhead [BB * HH * SQP * DD];    // rounded*0.125, pad rows 0
__device__ float g_attn  [MM * CC];               // rounded (by merge)
__device__ int   g_inv   [TOK_N];
__device__ float g_ml    [2 * 32 * NQT * 128 * 2];
__device__ float g_op    [2 * 32 * NQT * 128 * 64];

// ---------------- helpers ----------------
__device__ __forceinline__ unsigned f2tf(float x) {
    unsigned r;
    asm("cvt.rna.tf32.f32 %0, %1;" : "=r"(r) : "f"(x));
    return r;
}
__device__ __forceinline__ float f2tff(float x) {
    return __uint_as_float(f2tf(x));
}
__device__ __forceinline__ float4 round4(float4 v) {
    v.x = f2tff(v.x); v.y = f2tff(v.y); v.z = f2tff(v.z); v.w = f2tff(v.w);
    return v;
}
__device__ __forceinline__ void mma_tf32(float* c, const unsigned* a,
                                         unsigned b0, unsigned b1) {
    asm volatile(
        "mma.sync.aligned.m16n8k8.row.col.f32.tf32.tf32.f32 "
        "{%0,%1,%2,%3}, {%4,%5,%6,%7}, {%8,%9}, {%0,%1,%2,%3};"
        : "+f"(c[0]), "+f"(c[1]), "+f"(c[2]), "+f"(c[3])
        : "r"(a[0]), "r"(a[1]), "r"(a[2]), "r"(a[3]), "r"(b0), "r"(b1));
}
__device__ __forceinline__ void cp16(void* smem_dst, const void* gsrc) {
    unsigned sa = (unsigned)__cvta_generic_to_shared(smem_dst);
    asm volatile("cp.async.cg.shared.global [%0], [%1], 16;" :: "r"(sa), "l"(gsrc));
}
__device__ __forceinline__ void cp16z(void* smem_dst, const void* gsrc, bool pred) {
    unsigned sa = (unsigned)__cvta_generic_to_shared(smem_dst);
    int sz = pred ? 16 : 0;
    asm volatile("cp.async.cg.shared.global [%0], [%1], 16, %2;"
                 :: "r"(sa), "l"(gsrc), "r"(sz));
}
#define CP_COMMIT() asm volatile("cp.async.commit_group;")
#define CP_WAIT1()  asm volatile("cp.async.wait_group 1;")

// ---------------- inverse token map ----------------
__global__ void inv_init_kernel() {
    int i = blockIdx.x * blockDim.x + threadIdx.x;
    if (i < TOK_N) g_inv[i] = -1;
}
__global__ void inv_scatter_kernel(const int* __restrict__ tok) {
    int i = blockIdx.x * blockDim.x + threadIdx.x;
    if (i < NTOK_N) atomicMax(&g_inv[tok[i]], i);
}

// ---------------- prep: rounded copies of A rows and weights ----------------
#define PT1 (MM * CC / 4)             /* 640000 */
#define PT2 (PT1 + CC * N3C / 4)      /* +786432 */
#define PT3 (PT2 + CC * CC / 4)       /* +262144 = 1688576 */
__global__ void prep_kernel(const float* __restrict__ hid,
                            const float* __restrict__ enc,
                            const float* __restrict__ Wq,
                            const float* __restrict__ Wk,
                            const float* __restrict__ Wv,
                            const float* __restrict__ Wo) {
    int i = blockIdx.x * blockDim.x + threadIdx.x;
    if (i < PT1) {
        int r = i / (CC / 4), c4 = (i % (CC / 4)) * 4;
        int b = r / SQ, s = r % SQ;
        const float* src = (s < TEXT_N)
            ? enc + ((size_t)b * TEXT_N + s) * CC + c4
            : hid + ((size_t)b * NTOK_N + (s - TEXT_N)) * CC + c4;
        ((float4*)g_h)[i] = round4(*(const float4*)src);
    } else if (i < PT2) {
        int j = i - PT1;
        int k = j / (N3C / 4);
        int n = (j % (N3C / 4)) * 4;
        const float* src = (n < CC)   ? (Wq + (size_t)k * CC + n)
                         : (n < 2*CC) ? (Wk + (size_t)k * CC + (n - CC))
                                      : (Wv + (size_t)k * CC + (n - 2*CC));
        ((float4*)g_wqkv)[j] = round4(*(const float4*)src);
    } else if (i < PT3) {
        int j = i - PT2;
        ((float4*)g_wo)[j] = round4(((const float4*)Wo)[j]);
    }
}

// ---------------- GEMMs: 128x128 block, K-tile 32, cp.async double buffer ----
#define ASTR2 36
#define BSTR 136
#define GEMM_SMEM ((2*128*ASTR2 + 2*32*BSTR) * 4)   /* 71680 B */

__global__ __launch_bounds__(256) void gemm_qkv_mma() {
    extern __shared__ float smg[];
    float* As = smg;
    float* Bs = smg + 2 * 128 * ASTR2;
    const int tid = threadIdx.x;
    const int lane = tid & 31, wid = tid >> 5;
    const int g = lane >> 2, tig = lane & 3;
    const int wm = wid & 3, wn = wid >> 2;
    const int m0 = blockIdx.y * 128;
    const int n0 = blockIdx.x * 128;

    int ar[4], ac[4]; bool av[4];
#pragma unroll
    for (int k = 0; k < 4; k++) {
        int i = tid + 256 * k;
        ar[k] = i >> 3; ac[k] = (i & 7) << 2;
        av[k] = (m0 + ar[k]) < MM;
    }

    auto stage = [&](int kk, int st) {
        float* dA = As + st * 128 * ASTR2;
        float* dB = Bs + st * 32 * BSTR;
#pragma unroll
        for (int k = 0; k < 4; k++)
            cp16z(dA + ar[k]*ASTR2 + ac[k],
                  g_h + (size_t)(m0 + ar[k]) * CC + kk + ac[k], av[k]);
#pragma unroll
        for (int i = tid; i < 1024; i += 256) {
            int r = i >> 5, c4 = (i & 31) << 2;
            cp16(dB + r*BSTR + c4, g_wqkv + (size_t)(kk + r) * N3C + n0 + c4);
        }
    };

    float cacc[2][8][4];
#pragma unroll
    for (int i = 0; i < 2; i++)
#pragma unroll
        for (int j = 0; j < 8; j++)
#pragma unroll
            for (int v = 0; v < 4; v++) cacc[i][j][v] = 0.f;

    stage(0, 0);
    CP_COMMIT();

    for (int t = 0; t < 32; t++) {
        int st = t & 1;
        if (t + 1 < 32) stage((t + 1) * 32, st ^ 1);
        CP_COMMIT();
        CP_WAIT1();
        __syncthreads();
        float* pA = As + st * 128 * ASTR2;
        float* pB = Bs + st * 32 * BSTR;
#pragma unroll
        for (int ks2 = 0; ks2 < 4; ks2++) {
            const int k0 = ks2 * 8;
            unsigned af[2][4];
#pragma unroll
            for (int mf = 0; mf < 2; mf++) {
                int rbm = wm * 32 + mf * 16 + g;
                af[mf][0] = __float_as_uint(pA[rbm*ASTR2 + k0 + tig]);
                af[mf][1] = __float_as_uint(pA[(rbm+8)*ASTR2 + k0 + tig]);
                af[mf][2] = __float_as_uint(pA[rbm*ASTR2 + k0 + tig + 4]);
                af[mf][3] = __float_as_uint(pA[(rbm+8)*ASTR2 + k0 + tig + 4]);
            }
#pragma unroll
            for (int nf = 0; nf < 8; nf++) {
                int nc = wn * 64 + nf * 8 + g;
                unsigned b0 = __float_as_uint(pB[(k0+tig)*BSTR + nc]);
                unsigned b1 = __float_as_uint(pB[(k0+tig+4)*BSTR + nc]);
                mma_tf32(cacc[0][nf], af[0], b0, b1);
                mma_tf32(cacc[1][nf], af[1], b0, b1);
            }
        }
        __syncthreads();
    }

#pragma unroll
    for (int mf = 0; mf < 2; mf++) {
        int r0 = m0 + wm * 32 + mf * 16 + g;
#pragma unroll
        for (int nf = 0; nf < 8; nf++) {
            int col = n0 + wn * 64 + nf * 8 + 2 * tig;
            if (r0 < MM)
                *(float2*)(g_qkv + (size_t)r0 * N3C + col) =
                    make_float2(cacc[mf][nf][0], cacc[mf][nf][1]);
            if (r0 + 8 < MM)
                *(float2*)(g_qkv + (size_t)(r0 + 8) * N3C + col) =
                    make_float2(cacc[mf][nf][2], cacc[mf][nf][3]);
        }
    }
}

__global__ __launch_bounds__(256) void gemm_out_mma(const float* __restrict__ bo,
                                                    float* __restrict__ out) {
    extern __shared__ float smg[];
    float* As = smg;
    float* Bs = smg + 2 * 128 * ASTR2;
    const int tid = threadIdx.x;
    const int lane = tid & 31, wid = tid >> 5;
    const int g = lane >> 2, tig = lane & 3;
    const int wm = wid & 3, wn = wid >> 2;
    const int m0 = blockIdx.y * 128;
    const int n0 = blockIdx.x * 128;

    int ar[4], ac[4]; bool av[4];
#pragma unroll
    for (int k = 0; k < 4; k++) {
        int i = tid + 256 * k;
        ar[k] = i >> 3; ac[k] = (i & 7) << 2;
        av[k] = (m0 + ar[k]) < MM;
    }

    auto stage = [&](int kk, int st) {
        float* dA = As + st * 128 * ASTR2;
        float* dB = Bs + st * 32 * BSTR;
#pragma unroll
        for (int k = 0; k < 4; k++)
            cp16z(dA + ar[k]*ASTR2 + ac[k],
                  g_attn + (size_t)(m0 + ar[k]) * CC + kk + ac[k], av[k]);
#pragma unroll
        for (int i = tid; i < 1024; i += 256) {
            int r = i >> 5, c4 = (i & 31) << 2;
            cp16(dB + r*BSTR + c4, g_wo + (size_t)(kk + r) * CC + n0 + c4);
        }
    };

    float cacc[2][8][4];
#pragma unroll
    for (int i = 0; i < 2; i++)
#pragma unroll
        for (int j = 0; j < 8; j++)
#pragma unroll
            for (int v = 0; v < 4; v++) cacc[i][j][v] = 0.f;

    stage(0, 0);
    CP_COMMIT();

    for (int t = 0; t < 32; t++) {
        int st = t & 1;
        if (t + 1 < 32) stage((t + 1) * 32, st ^ 1);
        CP_COMMIT();
        CP_WAIT1();
        __syncthreads();
        float* pA = As + st * 128 * ASTR2;
        float* pB = Bs + st * 32 * BSTR;
#pragma unroll
        for (int ks2 = 0; ks2 < 4; ks2++) {
            const int k0 = ks2 * 8;
            unsigned af[2][4];
#pragma unroll
            for (int mf = 0; mf < 2; mf++) {
                int rbm = wm * 32 + mf * 16 + g;
                af[mf][0] = __float_as_uint(pA[rbm*ASTR2 + k0 + tig]);
                af[mf][1] = __float_as_uint(pA[(rbm+8)*ASTR2 + k0 + tig]);
                af[mf][2] = __float_as_uint(pA[rbm*ASTR2 + k0 + tig + 4]);
                af[mf][3] = __float_as_uint(pA[(rbm+8)*ASTR2 + k0 + tig + 4]);
            }
#pragma unroll
            for (int nf = 0; nf < 8; nf++) {
                int nc = wn * 64 + nf * 8 + g;
                unsigned b0 = __float_as_uint(pB[(k0+tig)*BSTR + nc]);
                unsigned b1 = __float_as_uint(pB[(k0+tig+4)*BSTR + nc]);
                mma_tf32(cacc[0][nf], af[0], b0, b1);
                mma_tf32(cacc[1][nf], af[1], b0, b1);
            }
        }
        __syncthreads();
    }

#pragma unroll
    for (int mf = 0; mf < 2; mf++) {
#pragma unroll
        for (int half = 0; half < 2; half++) {
            int row = m0 + wm * 32 + mf * 16 + g + half * 8;
            if (row >= MM) continue;
            int b = row / SQ, s = row % SQ;
            size_t off = (s >= TEXT_N)
                ? ((size_t)(b * NTOK_N + (s - TEXT_N))) * CC
                : (size_t)BB * NTOK_N * CC + ((size_t)(b * TEXT_N + s)) * CC;
#pragma unroll
            for (int nf = 0; nf < 8; nf++) {
                int col = n0 + wn * 64 + nf * 8 + 2 * tig;
                float2 t = make_float2(cacc[mf][nf][0 + 2*half] + bo[col],
                                       cacc[mf][nf][1 + 2*half] + bo[col + 1]);
                *(float2*)(out + off + col) = t;
            }
        }
    }
}

// ---------------- combined norm: Q + KV, rounded outputs ----------------
__global__ __launch_bounds__(512) void norm_kernel(const float* __restrict__ gq,
                                                   const float* __restrict__ bq,
                                                   const float* __restrict__ gk,
                                                   const float* __restrict__ bk,
                                                   const float* __restrict__ rc,
                                                   const float* __restrict__ rs,
                                                   const float* __restrict__ kc,
                                                   const float* __restrict__ vc,
                                                   const int* __restrict__ tok) {
    const int bid = blockIdx.x;
    const int w = threadIdx.x >> 5;
    const int lid = threadIdx.x & 31;

    if (bid < BB * SKV) {
        // ---- K/V path ----
        const int b = bid / SKV, p = bid % SKV;
        const float* ksrc; const float* vsrc;
        if (p < TEXT_N) {
            size_t row = ((size_t)(b * SQ + p)) * N3C;
            ksrc = g_qkv + row + CC; vsrc = g_qkv + row + 2*CC;
        } else {
            int i = g_inv[p - TEXT_N];
            if (i >= 0) {
                size_t row = ((size_t)(b * SQ + TEXT_N + i)) * N3C;
                ksrc = g_qkv + row + CC; vsrc = g_qkv + row + 2*CC;
            } else {
                size_t row = ((size_t)(b * SKV + p)) * CC;
                ksrc = kc + row; vsrc = vc + row;
            }
        }
        float2 x = *(const float2*)(ksrc + w * DD + 2 * lid);
        float sum = x.x + x.y;
        float sq  = x.x * x.x + x.y * x.y;
#pragma unroll
        for (int off = 16; off; off >>= 1) {
            sum += __shfl_xor_sync(0xffffffffu, sum, off);
            sq  += __shfl_xor_sync(0xffffffffu, sq,  off);
        }
        float mean = sum * (1.0f / 64.0f);
        float var  = sq * (1.0f / 64.0f) - mean * mean;
        float rsig = rsqrtf(var + 1e-6f);
        float y0 = (x.x - mean) * rsig * gk[2*lid]   + bk[2*lid];
        float y1 = (x.y - mean) * rsig * gk[2*lid+1] + bk[2*lid+1];
        float o0 = y0, o1 = y1;
        if (p >= TEXT_N) {
            int rp = p - TEXT_N;
            float2 c  = *(const float2*)(rc + (size_t)rp * DD + 2 * lid);
            float2 sn = *(const float2*)(rs + (size_t)rp * DD + 2 * lid);
            o0 = y0 * c.x - y1 * sn.x;
            o1 = y1 * c.y + y0 * sn.y;
        }
        int bh = b * HH + w;
        size_t ob = ((size_t)bh * SKVP + p) * DD + 2 * lid;
        *(float2*)(g_khead + ob) = make_float2(f2tff(o0), f2tff(o1));
        float2 v = *(const float2*)(vsrc + w * DD + 2 * lid);
        *(float2*)(g_vhead + ob) = make_float2(f2tff(v.x), f2tff(v.y));
    } else {
        // ---- Q path ----
        const int bs = bid - BB * SKV;
        const int b = bs / SQ, s = bs % SQ;
        size_t base = (size_t)bs * N3C + w * DD + 2 * lid;
        float2 x = *(const float2*)(g_qkv + base);
        float sum = x.x + x.y;
        float sq  = x.x * x.x + x.y * x.y;
#pragma unroll
        for (int off = 16; off; off >>= 1) {
            sum += __shfl_xor_sync(0xffffffffu, sum, off);
            sq  += __shfl_xor_sync(0xffffffffu, sq,  off);
        }
        float mean = sum * (1.0f / 64.0f);
        float var  = sq * (1.0f / 64.0f) - mean * mean;
        float rsig = rsqrtf(var + 1e-6f);
        float y0 = (x.x - mean) * rsig * gq[2*lid]   + bq[2*lid];
        float y1 = (x.y - mean) * rsig * gq[2*lid+1] + bq[2*lid+1];
        float o0 = y0, o1 = y1;
        if (s >= TEXT_N) {
            int rp = tok[s - TEXT_N];
            float2 c  = *(const float2*)(rc + (size_t)rp * DD + 2 * lid);
            float2 sn = *(const float2*)(rs + (size_t)rp * DD + 2 * lid);
            o0 = y0 * c.x - y1 * sn.x;
            o1 = y1 * c.y + y0 * sn.y;
        }
        *(float2*)(g_qhead + ((size_t)(b * HH + w) * SQP + s) * DD + 2 * lid) =
            make_float2(f2tff(o0 * 0.125f), f2tff(o1 * 0.125f));
    }
}

// ---------------- flash attention: 128-row q tiles, split-KV x2 ----------------
#define KTSTR 68
#define VTSTR 72
#define BUFSZ (64*KTSTR + 64*VTSTR)          /* 8960 floats */
#define PSOFF (2*BUFSZ)                       /* 17920 floats */
#define ATTN_SMEM ((PSOFF + 128*KTSTR) * 4)   /* 106496 B */

__global__ __launch_bounds__(256, 2) void attn_mma_kernel() {
    extern __shared__ float sm[];
    float* Ps = sm + PSOFF;   // 128 x KTSTR (Q staging, then P)

    const int bh = blockIdx.x;
    const int qt = blockIdx.y;
    const int split = blockIdx.z;
    const int q0 = qt * 128;
    const int tid = threadIdx.x;
    const int w = tid >> 5, lane = tid & 31;
    const int g = lane >> 2, tig = lane & 3;
    const int rb = w * 16 + g;

    const float* kbase = g_khead + (size_t)bh * SKVP * DD;
    const float* vbase = g_vhead + (size_t)bh * SKVP * DD;
    const float* qbase = g_qhead + ((size_t)bh * SQP + q0) * DD;

    const int t0 = split * KSPLIT, t1 = t0 + KSPLIT;

    auto stage_kv = [&](float* dst, int kt) {
#pragma unroll
        for (int i = tid; i < 2048; i += 256) {
            int half = i >> 10, j = i & 1023;
            int r = j >> 4, c4 = (j & 15) << 2;
            if (half)
                cp16(dst + 64*KTSTR + r * VTSTR + c4,
                     vbase + (size_t)(kt + r) * DD + c4);
            else
                cp16(dst + r * KTSTR + c4,
                     kbase + (size_t)(kt + r) * DD + c4);
        }
    };

    // stage Q (group 1), then first KV tile (group 2)
#pragma unroll
    for (int i = tid; i < 2048; i += 256) {
        int r = i >> 4, c4 = (i & 15) << 2;
        cp16(Ps + r * KTSTR + c4, qbase + r * DD + c4);
    }
    CP_COMMIT();
    stage_kv(sm, t0 * 64);
    CP_COMMIT();
    CP_WAIT1();            // Q ready
    __syncthreads();

    unsigned qf[8][4];
#pragma unroll
    for (int ks = 0; ks < 8; ks++) {
        int k0 = ks * 8;
        qf[ks][0] = __float_as_uint(Ps[rb * KTSTR + k0 + tig]);
        qf[ks][1] = __float_as_uint(Ps[(rb + 8) * KTSTR + k0 + tig]);
        qf[ks][2] = __float_as_uint(Ps[rb * KTSTR + k0 + tig + 4]);
        qf[ks][3] = __float_as_uint(Ps[(rb + 8) * KTSTR + k0 + tig + 4]);
    }
    __syncthreads();   // Ps now reusable as P buffer

    float oacc[8][4];
#pragma unroll
    for (int nf = 0; nf < 8; nf++)
#pragma unroll
        for (int v = 0; v < 4; v++) oacc[nf][v] = 0.f;
    float mx0 = -1e30f, mx1 = -1e30f, l0 = 0.f, l1 = 0.f;

    for (int t = t0; t < t1; t++) {
        int st = (t - t0) & 1;
        if (t + 1 < t1) stage_kv(sm + (st ^ 1) * BUFSZ, (t + 1) * 64);
        CP_COMMIT();
        CP_WAIT1();
        __syncthreads();
        float* Ks = sm + st * BUFSZ;
        float* Vs = Ks + 64 * KTSTR;
        const int kt = t * 64;

        // S = Q K^T
        float sacc[8][4];
#pragma unroll
        for (int nf = 0; nf < 8; nf++)
#pragma unroll
            for (int v = 0; v < 4; v++) sacc[nf][v] = 0.f;
#pragma unroll
        for (int nf = 0; nf < 8; nf++) {
            int rn = (nf * 8 + g) * KTSTR;
#pragma unroll
            for (int ks = 0; ks < 8; ks++) {
                unsigned b0 = __float_as_uint(Ks[rn + ks * 8 + tig]);
                unsigned b1 = __float_as_uint(Ks[rn + ks * 8 + tig + 4]);
                mma_tf32(sacc[nf], qf[ks], b0, b1);
            }
        }

        // mask tail columns
        if (kt + 64 > SKV) {
#pragma unroll
            for (int nf = 0; nf < 8; nf++) {
                int c = kt + nf * 8 + 2 * tig;
                if (c >= SKV)     { sacc[nf][0] = -1e30f; sacc[nf][2] = -1e30f; }
                if (c + 1 >= SKV) { sacc[nf][1] = -1e30f; sacc[nf][3] = -1e30f; }
            }
        }

        // online softmax (rows rb, rb+8)
        float tmax0 = -1e30f, tmax1 = -1e30f;
#pragma unroll
        for (int nf = 0; nf < 8; nf++) {
            tmax0 = fmaxf(tmax0, fmaxf(sacc[nf][0], sacc[nf][1]));
            tmax1 = fmaxf(tmax1, fmaxf(sacc[nf][2], sacc[nf][3]));
        }
        tmax0 = fmaxf(tmax0, __shfl_xor_sync(0xffffffffu, tmax0, 1));
        tmax0 = fmaxf(tmax0, __shfl_xor_sync(0xffffffffu, tmax0, 2));
        tmax1 = fmaxf(tmax1, __shfl_xor_sync(0xffffffffu, tmax1, 1));
        tmax1 = fmaxf(tmax1, __shfl_xor_sync(0xffffffffu, tmax1, 2));
        float mn0 = fmaxf(mx0, tmax0), mn1 = fmaxf(mx1, tmax1);
        float corr0 = __expf(mx0 - mn0), corr1 = __expf(mx1 - mn1);
        mx0 = mn0; mx1 = mn1;

        float tsum0 = 0.f, tsum1 = 0.f;
#pragma unroll
        for (int nf = 0; nf < 8; nf++) {
            float p00 = __expf(sacc[nf][0] - mn0);
            float p01 = __expf(sacc[nf][1] - mn0);
            float p10 = __expf(sacc[nf][2] - mn1);
            float p11 = __expf(sacc[nf][3] - mn1);
            tsum0 += p00 + p01; tsum1 += p10 + p11;
            int c = nf * 8 + 2 * tig;
            *(float2*)(Ps + rb * KTSTR + c) = make_float2(f2tff(p00), f2tff(p01));
            *(float2*)(Ps + (rb + 8) * KTSTR + c) = make_float2(f2tff(p10), f2tff(p11));
        }
        tsum0 += __shfl_xor_sync(0xffffffffu, tsum0, 1);
        tsum0 += __shfl_xor_sync(0xffffffffu, tsum0, 2);
        tsum1 += __shfl_xor_sync(0xffffffffu, tsum1, 1);
        tsum1 += __shfl_xor_sync(0xffffffffu, tsum1, 2);
        l0 = l0 * corr0 + tsum0;
        l1 = l1 * corr1 + tsum1;
#pragma unroll
        for (int nf = 0; nf < 8; nf++) {
            oacc[nf][0] *= corr0; oacc[nf][1] *= corr0;
            oacc[nf][2] *= corr1; oacc[nf][3] *= corr1;
        }
        __syncwarp();

        // O += P V  (B frags from natural-layout V, stride 72: conflict-free)
#pragma unroll
        for (int ks = 0; ks < 8; ks++) {
            int j0 = ks * 8;
            unsigned pf[4];
            pf[0] = __float_as_uint(Ps[rb * KTSTR + j0 + tig]);
            pf[1] = __float_as_uint(Ps[(rb + 8) * KTSTR + j0 + tig]);
            pf[2] = __float_as_uint(Ps[rb * KTSTR + j0 + tig + 4]);
            pf[3] = __float_as_uint(Ps[(rb + 8) * KTSTR + j0 + tig + 4]);
#pragma unroll
            for (int nf = 0; nf < 8; nf++) {
                unsigned b0 = __float_as_uint(Vs[(j0 + tig) * VTSTR + nf * 8 + g]);
                unsigned b1 = __float_as_uint(Vs[(j0 + tig + 4) * VTSTR + nf * 8 + g]);
                mma_tf32(oacc[nf], pf, b0, b1);
            }
        }
        __syncthreads();
    }

    // split epilogue: unnormalized O + (m, l)
    const int bhqt = bh * NQT + qt;
    const size_t obase = ((size_t)(split * 32 * NQT + bhqt)) * 128 * 64;
#pragma unroll
    for (int nf = 0; nf < 8; nf++) {
        int col = nf * 8 + 2 * tig;
        *(float2*)(g_op + obase + (size_t)rb * 64 + col) =
            make_float2(oacc[nf][0], oacc[nf][1]);
        *(float2*)(g_op + obase + (size_t)(rb + 8) * 64 + col) =
            make_float2(oacc[nf][2], oacc[nf][3]);
    }
    if (tig == 0) {
        size_t mb = ((size_t)(split * 32 * NQT + bhqt)) * 128 * 2;
        g_ml[mb + rb * 2]           = mx0;
        g_ml[mb + rb * 2 + 1]       = l0;
        g_ml[mb + (rb + 8) * 2]     = mx1;
        g_ml[mb + (rb + 8) * 2 + 1] = l1;
    }
}

// ---------------- merge the two KV splits (writes rounded g_attn) ----------------
__global__ void attn_merge_kernel() {
    int idx = blockIdx.x * blockDim.x + threadIdx.x;
    const int total = 32 * NQT * 128 * 32;
    if (idx >= total) return;
    int lane = idx & 31;
    int row = idx >> 5;
    int r = row & 127;
    int bhqt = row >> 7;
    int qt = bhqt % NQT, bh = bhqt / NQT;
    int qr = qt * 128 + r;
    if (qr >= SQ) return;
    size_t mb0 = (size_t)bhqt * 256 + r * 2;
    size_t mb1 = (size_t)(32 * NQT + bhqt) * 256 + r * 2;
    float m0 = g_ml[mb0], la = g_ml[mb0 + 1];
    float m1 = g_ml[mb1], lb = g_ml[mb1 + 1];
    float m = fmaxf(m0, m1);
    float c0 = __expf(m0 - m), c1 = __expf(m1 - m);
    float inv = 1.0f / (la * c0 + lb * c1);
    float2 a = *(const float2*)(g_op + ((size_t)bhqt * 128 + r) * 64 + 2 * lane);
    float2 bv = *(const float2*)(g_op + ((size_t)(32 * NQT + bhqt) * 128 + r) * 64 + 2 * lane);
    int b = bh >> 4, h = bh & 15;
    *(float2*)(g_attn + ((size_t)(b * SQ + qr)) * CC + h * DD + 2 * lane) =
        make_float2(f2tff((a.x * c0 + bv.x * c1) * inv),
                    f2tff((a.y * c0 + bv.y * c1) * inv));
}

// ---------------- launch ----------------
extern "C" void kernel_launch(void* const* d_in, const int* in_sizes, int n_in,
                              void* d_out, int out_size) {
    const float* hid = (const float*)d_in[0];
    const float* enc = (const float*)d_in[1];
    const float* Wq  = (const float*)d_in[2];
    const float* Wk  = (const float*)d_in[3];
    const float* Wv  = (const float*)d_in[4];
    const float* Wo  = (const float*)d_in[5];
    const float* bo  = (const float*)d_in[6];
    const float* gq  = (const float*)d_in[7];
    const float* bq  = (const float*)d_in[8];
    const float* gk  = (const float*)d_in[9];
    const float* bk  = (const float*)d_in[10];
    const float* rc  = (const float*)d_in[11];
    const float* rs  = (const float*)d_in[12];
    const float* kc  = (const float*)d_in[13];
    const float* vc  = (const float*)d_in[14];
    const int*   tok = (const int*)d_in[15];
    float* out = (float*)d_out;

    cudaFuncSetAttribute(gemm_qkv_mma,
                         cudaFuncAttributeMaxDynamicSharedMemorySize, GEMM_SMEM);
    cudaFuncSetAttribute(gemm_out_mma,
                         cudaFuncAttributeMaxDynamicSharedMemorySize, GEMM_SMEM);
    cudaFuncSetAttribute(attn_mma_kernel,
                         cudaFuncAttributeMaxDynamicSharedMemorySize, ATTN_SMEM);

    inv_init_kernel<<<(TOK_N + 255) / 256, 256>>>();                       // 1
    inv_scatter_kernel<<<(NTOK_N + 255) / 256, 256>>>(tok);                // 2
    prep_kernel<<<(PT3 + 255) / 256, 256>>>(hid, enc, Wq, Wk, Wv, Wo);     // 3
    gemm_qkv_mma<<<dim3(N3C / 128, (MM + 127) / 128), 256, GEMM_SMEM>>>(); // 4
    norm_kernel<<<BB * SKV + BB * SQ, 512>>>(gq, bq, gk, bk, rc, rs,
                                             kc, vc, tok);                 // 5
    attn_mma_kernel<<<dim3(BB * HH, NQT, 2), 256, ATTN_SMEM>>>();          // 6 (ncu)
    attn_merge_kernel<<<(32 * NQT * 128 * 32 + 255) / 256, 256>>>();       // 7
    gemm_out_mma<<<dim3(CC / 128, (MM + 127) / 128), 256, GEMM_SMEM>>>(bo, out); // 8
}